// round 11
// baseline (speedup 1.0000x reference)
#include <cuda_runtime.h>
#include <cuda_fp16.h>
#include <math.h>
#include <stdint.h>

constexpr int B_  = 2;
constexpr int C_  = 1024;
constexpr int H_  = 16;
constexpr int N_  = 64;
constexpr int LI_ = 4096;
constexpr int LT_ = 512;
constexpr int L_  = LI_ + LT_;   // 4608
constexpr int HID_ = 2048;

constexpr size_t XSZ   = (size_t)B_ * C_ * L_;
constexpr size_t IMGSZ = (size_t)B_ * C_ * LI_;
constexpr size_t TXTSZ = (size_t)B_ * C_ * LT_;

// ---------------- static scratch ----------------
__device__ float g_mod[2 * B_ * 6 * C_];
__device__ float g_inv[B_ * L_];
__device__ float g_gate[XSZ];                        // silu(g) in (B,L,C)
__device__ float g_r[XSZ];                           // (B,H,L,N)
__device__ float g_k[XSZ];
__device__ float g_v[XSZ];
__device__ float g_y[XSZ];
__device__ float g_attn[XSZ];                        // (B,C,L)
__device__ float g_img1[IMGSZ];
__device__ float g_txt1[TXTSZ];
__device__ float g_himg[IMGSZ];
__device__ float g_htxt[TXTSZ];

// fp16 GEMM operands
__device__ __half g_Arkvg[(size_t)4096 * 1024];      // [Wr;Wk;Wv;Wg]
__device__ __half g_Awo [(size_t)1024 * 1024];
__device__ __half g_Afi1[(size_t)2048 * 1024];
__device__ __half g_Afi2[(size_t)1024 * 2048];
__device__ __half g_Aft1[(size_t)2048 * 1024];
__device__ __half g_Aft2[(size_t)1024 * 2048];
__device__ __half g_Bx4[(size_t)4 * B_ * L_ * 1024]; // mixed inputs per part p
__device__ __half g_Bz [(size_t)B_ * L_  * 1024];
__device__ __half g_Bhi[(size_t)B_ * LI_ * 1024];
__device__ __half g_Bht[(size_t)B_ * LT_ * 1024];
__device__ __half g_Bmi[(size_t)B_ * LI_ * 2048];
__device__ __half g_Bmt[(size_t)B_ * LT_ * 2048];

// ---------------- helpers ----------------
__device__ __forceinline__ uint32_t smem_u32(const void* p) {
    uint32_t r;
    asm("{ .reg .u64 t; cvta.to.shared.u64 t, %1; cvt.u32.u64 %0, t; }" : "=r"(r) : "l"(p));
    return r;
}
__device__ __forceinline__ void cp16(uint32_t s, const void* g) {
    asm volatile("cp.async.cg.shared.global [%0], [%1], 16;" :: "r"(s), "l"(g));
}
__device__ __forceinline__ void ldsm4(uint32_t* r, uint32_t addr) {
    asm volatile("ldmatrix.sync.aligned.m8n8.x4.shared.b16 {%0,%1,%2,%3},[%4];"
                 : "=r"(r[0]), "=r"(r[1]), "=r"(r[2]), "=r"(r[3]) : "r"(addr));
}
__device__ __forceinline__ void mma16816(float* d, const uint32_t* a, const uint32_t* b) {
    asm volatile("mma.sync.aligned.m16n8k16.row.col.f32.f16.f16.f32 "
                 "{%0,%1,%2,%3},{%4,%5,%6,%7},{%8,%9},{%0,%1,%2,%3};"
                 : "+f"(d[0]), "+f"(d[1]), "+f"(d[2]), "+f"(d[3])
                 : "r"(a[0]), "r"(a[1]), "r"(a[2]), "r"(a[3]), "r"(b[0]), "r"(b[1]));
}

// ---------------- prep: modulation (silu inline) + rms sums ----------------
constexpr int MOD_BLOCKS = (2 * 6 * C_) / 8;
constexpr int RMS_BLOCKS = (B_ * L_) / 256;

__global__ void prep_k(const float* __restrict__ cond,
                       const float* __restrict__ Wimg, const float* __restrict__ bimg,
                       const float* __restrict__ Wtxt, const float* __restrict__ btxt,
                       const float* __restrict__ img, const float* __restrict__ txt,
                       float* __restrict__ modout, float* __restrict__ invout) {
    if (blockIdx.x < MOD_BLOCKS) {
        int gw = (blockIdx.x * 256 + threadIdx.x) >> 5;
        int lane = threadIdx.x & 31;
        int s = gw / (6 * C_), o = gw % (6 * C_);
        const float* Wp = (s ? Wtxt : Wimg) + (size_t)o * C_;
        float a0 = 0.f, a1 = 0.f;
        for (int c = lane; c < C_; c += 32) {
            float wv = Wp[c];
            float c0 = cond[c], c1 = cond[C_ + c];
            a0 += wv * (c0 / (1.f + expf(-c0)));
            a1 += wv * (c1 / (1.f + expf(-c1)));
        }
        #pragma unroll
        for (int off = 16; off; off >>= 1) {
            a0 += __shfl_down_sync(0xffffffffu, a0, off);
            a1 += __shfl_down_sync(0xffffffffu, a1, off);
        }
        if (lane == 0) {
            float bb = (s ? btxt : bimg)[o];
            modout[(s * B_ + 0) * 6 * C_ + o] = a0 + bb;
            modout[(s * B_ + 1) * 6 * C_ + o] = a1 + bb;
        }
    } else {
        int gid = (blockIdx.x - MOD_BLOCKS) * 256 + threadIdx.x;
        if (gid >= B_ * L_) return;
        int b = gid / L_, l = gid % L_;
        const float* src; int Ls, li;
        if (l < LI_) { src = img; Ls = LI_; li = l; }
        else         { src = txt; Ls = LT_; li = l - LI_; }
        const float* sp = src + (size_t)b * C_ * Ls + li;
        float ss = 0.f;
        #pragma unroll 8
        for (int c = 0; c < C_; c++) { float v = sp[(size_t)c * Ls]; ss += v * v; }
        invout[gid] = rsqrtf(ss * (1.f / C_) + 1e-6f);
    }
}

// ---------------- weight packs ----------------
__global__ void wpack4_k(const float* __restrict__ Wr, const float* __restrict__ Wk,
                         const float* __restrict__ Wv, const float* __restrict__ Wg,
                         __half* __restrict__ A) {
    size_t idx = (size_t)blockIdx.x * 256 + threadIdx.x;
    if (idx >= (size_t)4 * 1024 * 1024) return;
    int p = (int)(idx >> 20);
    size_t rest = idx & 0xFFFFF;
    const float* W = (p == 0) ? Wr : (p == 1) ? Wk : (p == 2) ? Wv : Wg;
    A[idx] = __float2half(W[rest]);
}

__global__ void wsplit1_plain_k(const float* __restrict__ W, __half* __restrict__ A,
                                size_t total) {
    size_t idx = (size_t)blockIdx.x * 256 + threadIdx.x;
    if (idx < total) A[idx] = __float2half(W[idx]);
}

// ---------------- Bx4 build: rms-modulate + mix + transpose ----------------
__global__ void __launch_bounds__(256)
bxmix_k(const float* __restrict__ img, const float* __restrict__ txt,
        const float* __restrict__ rmswi, const float* __restrict__ rmswt,
        const float* __restrict__ mod, const float* __restrict__ inv,
        const float* __restrict__ mur, const float* __restrict__ muk,
        const float* __restrict__ muv, const float* __restrict__ mug,
        __half* __restrict__ out) {
    __shared__ float tileM[32][35];
    int b = blockIdx.z, c0 = blockIdx.y * 32, l0 = blockIdx.x * 32;
    int tx = threadIdx.x & 31, wy = threadIdx.x >> 5;
    int s0 = (l0 < LI_) ? 0 : 1;
    const float* src0 = s0 ? txt : img;
    int Ls0 = s0 ? LT_ : LI_;
    int li0 = s0 ? l0 - LI_ : l0;
    const float* mb0 = mod + (s0 * B_ + b) * 6 * C_;
    const float* rw0 = s0 ? rmswt : rmswi;
    float ivl = inv[b * L_ + l0 + tx];
    #pragma unroll
    for (int i = 0; i < 4; i++) {
        int c = wy + i * 8;
        int cg = c0 + c;
        float raw = src0[((size_t)b * C_ + cg) * Ls0 + li0 + tx];
        tileM[c][1 + tx] = raw * ivl * rw0[cg] * (1.f + mb0[C_ + cg]) + mb0[cg];
        if (tx == 0) {
            float pv = 0.f;
            if (l0 > 0) {
                int lm = l0 - 1;
                int sm = (lm < LI_) ? 0 : 1;
                const float* srcm = sm ? txt : img;
                int Lsm = sm ? LT_ : LI_;
                int lim = sm ? lm - LI_ : lm;
                const float* mbm = mod + (sm * B_ + b) * 6 * C_;
                const float* rwm = sm ? rmswt : rmswi;
                float rm = srcm[((size_t)b * C_ + cg) * Lsm + lim];
                pv = rm * inv[b * L_ + lm] * rwm[cg] * (1.f + mbm[C_ + cg]) + mbm[cg];
            }
            tileM[c][0] = pv;
        }
    }
    __syncthreads();
    int cg = c0 + tx;
    float m_r = mur[cg], m_k = muk[cg], m_v = muv[cg], m_g = mug[cg];
    const size_t PSTR = (size_t)B_ * L_ * 1024;
    #pragma unroll
    for (int i = 0; i < 4; i++) {
        int lrel = wy + i * 8;
        float vl = tileM[tx][1 + lrel];
        float vp = tileM[tx][lrel];
        float d = vp - vl;
        size_t base = ((size_t)b * L_ + l0 + lrel) * 1024 + cg;
        out[base]            = __float2half(vl + m_r * d);
        out[base + PSTR]     = __float2half(vl + m_k * d);
        out[base + 2 * PSTR] = __float2half(vl + m_v * d);
        out[base + 3 * PSTR] = __float2half(vl + m_g * d);
    }
}

// ---------------- activation transpose (fp32 -> fp16 (B,L,CR)) ----------------
__global__ void __launch_bounds__(256)
asplit1_k(const float* __restrict__ in, __half* __restrict__ out, int CR, int LL) {
    __shared__ float tile[32][33];
    int b = blockIdx.z, c0 = blockIdx.y * 32, l0 = blockIdx.x * 32;
    int tx = threadIdx.x & 31, wy = threadIdx.x >> 5;
    const float* ip = in + ((size_t)b * CR + c0) * LL + l0;
    #pragma unroll
    for (int i = 0; i < 4; i++) { int c = wy + i * 8; tile[c][tx] = ip[(size_t)c * LL + tx]; }
    __syncthreads();
    #pragma unroll
    for (int i = 0; i < 4; i++) {
        int l = wy + i * 8;
        out[((size_t)b * LL + l0 + l) * CR + (c0 + tx)] = __float2half(tile[tx][l]);
    }
}

// ---------------- mma.sync GEMM: 128m x 256l tile, 8 warps of 64x64 ----------------
constexpr int ASTG = 128 * 144;       // 18432
constexpr int BSTG = 256 * 144;       // 36864
constexpr int GSMEM = 3 * (ASTG + BSTG);   // 165888

// MODE 0: plain fp32 (B,M,L). MODE 1: rkvg -> r/k/v (B,H,L,N) + gate(B,L,C)
// MODE 2: gelu -> fp16 (B,L,M). MODE 3: resid + gate -> fp32 (B,M,L)
template <int MODE>
__global__ void __launch_bounds__(256, 1)
gemm_mma(const __half* __restrict__ A, const __half* __restrict__ Bm,
         float* __restrict__ Y, __half* __restrict__ Yh,
         float* __restrict__ ro, float* __restrict__ ko, float* __restrict__ vo,
         float* __restrict__ go,
         const float* __restrict__ resid, const float* __restrict__ gmod,
         int M, int K, int Llen) {
    extern __shared__ __align__(16) char dsmem[];
    uint32_t sb = smem_u32(dsmem);
    uint32_t sbB = sb + 3 * ASTG;
    int tid = threadIdx.x, lane = tid & 31, wid = tid >> 5;
    int wm = wid & 1, wn = wid >> 1;          // warp tile 64m x 64l
    int bz = blockIdx.z, l0 = blockIdx.x * 256, m0 = blockIdx.y * 128;
    const int NT = K >> 6;

    float acc[4][8][4] = {};
    const __half* Ag = A + (size_t)m0 * K;
    const __half* Bg;
    if (MODE == 1) {
        int part = m0 >> 10;
        Bg = Bm + (((size_t)(part * B_ + bz)) * Llen + l0) * K;
    } else {
        Bg = Bm + ((size_t)bz * Llen + l0) * K;
    }

    // A: thread -> half-row (row tid>>1, seg tid&1);  B: thread -> full row tid
    uint32_t aoff = (uint32_t)((tid >> 1) * 144 + (tid & 1) * 64);
    uint32_t boff = (uint32_t)(tid * 144);
    const __half* Agr = Ag + (size_t)(tid >> 1) * K + (tid & 1) * 32;
    const __half* Bgr = Bg + (size_t)tid * K;

    #pragma unroll
    for (int t = 0; t < 2; t++) {
        uint32_t ao = sb + t * ASTG + aoff;
        uint32_t bo = sbB + t * BSTG + boff;
        #pragma unroll
        for (int j = 0; j < 4; j++) cp16(ao + j * 16, Agr + t * 64 + j * 8);
        #pragma unroll
        for (int j = 0; j < 8; j++) cp16(bo + j * 16, Bgr + t * 64 + j * 8);
        asm volatile("cp.async.commit_group;");
    }

    for (int it = 0; it < NT; it++) {
        if (it + 1 < NT) asm volatile("cp.async.wait_group 1;");
        else             asm volatile("cp.async.wait_group 0;");
        __syncthreads();
        if (it + 2 < NT) {
            int st = (it + 2) % 3;
            int ka = (it + 2) * 64;
            uint32_t ao = sb + st * ASTG + aoff;
            uint32_t bo = sbB + st * BSTG + boff;
            #pragma unroll
            for (int j = 0; j < 4; j++) cp16(ao + j * 16, Agr + ka + j * 8);
            #pragma unroll
            for (int j = 0; j < 8; j++) cp16(bo + j * 16, Bgr + ka + j * 8);
            asm volatile("cp.async.commit_group;");
        }
        uint32_t baseA = sb + (it % 3) * ASTG;
        uint32_t baseB = sbB + (it % 3) * BSTG;
        #pragma unroll
        for (int kk = 0; kk < 4; kk++) {
            uint32_t a[4][4], bq[4][4];
            #pragma unroll
            for (int ma = 0; ma < 4; ma++)
                ldsm4(a[ma], baseA + (wm * 64 + ma * 16 + (lane & 15)) * 144
                              + kk * 32 + (lane >> 4) * 16);
            #pragma unroll
            for (int nb = 0; nb < 4; nb++)
                ldsm4(bq[nb], baseB + (wn * 64 + nb * 16 + (lane & 7) + ((lane >> 4) & 1) * 8) * 144
                               + kk * 32 + ((lane >> 3) & 1) * 16);
            #pragma unroll
            for (int ma = 0; ma < 4; ma++)
                #pragma unroll
                for (int na = 0; na < 8; na++)
                    mma16816(acc[ma][na], a[ma], &bq[na >> 1][(na & 1) * 2]);
        }
    }

    if (MODE == 0 || MODE == 3) {
        #pragma unroll
        for (int ma = 0; ma < 4; ma++) {
            #pragma unroll
            for (int hf = 0; hf < 2; hf++) {
                int m = m0 + wm * 64 + ma * 16 + (lane >> 2) + hf * 8;
                size_t ybase = ((size_t)bz * M + m) * Llen;
                float gm = 0.f;
                if (MODE == 3) gm = gmod[bz * 6 * C_ + m];
                #pragma unroll
                for (int na = 0; na < 8; na++) {
                    int col = l0 + wn * 64 + na * 8 + 2 * (lane & 3);
                    float v0 = acc[ma][na][hf * 2], v1 = acc[ma][na][hf * 2 + 1];
                    if (MODE == 3) {
                        float2 rr = *(const float2*)(resid + ybase + col);
                        v0 = rr.x + gm * v0;
                        v1 = rr.y + gm * v1;
                    }
                    *(float2*)(Y + ybase + col) = make_float2(v0, v1);
                }
            }
        }
    } else if (MODE == 1) {
        __syncthreads();
        float* st = (float*)dsmem;      // [256 l][132]
        int part = m0 >> 10;
        int c0 = m0 & 1023;
        #pragma unroll
        for (int ma = 0; ma < 4; ma++)
            #pragma unroll
            for (int na = 0; na < 8; na++)
                #pragma unroll
                for (int e = 0; e < 4; e++) {
                    int hf = e >> 1, j = e & 1;
                    int m = wm * 64 + ma * 16 + (lane >> 2) + hf * 8;
                    int l = wn * 64 + na * 8 + 2 * (lane & 3) + j;
                    float v = acc[ma][na][hf * 2 + j];
                    if (part == 3) v = v / (1.f + expf(-v));
                    st[l * 132 + m] = v;
                }
        __syncthreads();
        int l = tid;
        if (part < 3) {
            float* outb = (part == 0) ? ro : (part == 1) ? ko : vo;
            #pragma unroll
            for (int sg = 0; sg < 2; sg++) {
                int c = c0 + sg * 64;
                const float* sp = st + l * 132 + sg * 64;
                float* op = outb + ((size_t)(bz * H_ + (c >> 6)) * L_ + l0 + l) * 64;
                #pragma unroll
                for (int j = 0; j < 64; j += 4)
                    *(float4*)(op + j) = *(const float4*)(sp + j);
            }
        } else {
            const float* sp = st + l * 132;
            float* op = go + ((size_t)bz * L_ + l0 + l) * C_ + c0;
            #pragma unroll
            for (int j = 0; j < 128; j += 4)
                *(float4*)(op + j) = *(const float4*)(sp + j);
        }
    } else { // MODE 2: gelu -> fp16 (B,L,M)
        __syncthreads();
        __half* st = (__half*)dsmem;    // [256 l][136]
        #pragma unroll
        for (int ma = 0; ma < 4; ma++)
            #pragma unroll
            for (int na = 0; na < 8; na++)
                #pragma unroll
                for (int e = 0; e < 4; e++) {
                    int hf = e >> 1, j = e & 1;
                    int m = wm * 64 + ma * 16 + (lane >> 2) + hf * 8;
                    int l = wn * 64 + na * 8 + 2 * (lane & 3) + j;
                    float v = acc[ma][na][hf * 2 + j];
                    float t = 0.7978845608f * (v + 0.044715f * v * v * v);
                    v = 0.5f * v * (1.f + tanhf(t));
                    st[l * 136 + m] = __float2half(v);
                }
        __syncthreads();
        int l = tid;
        const uint4* sp = (const uint4*)(st + l * 136);
        uint4* op = (uint4*)(Yh + ((size_t)bz * Llen + l0 + l) * M + m0);
        #pragma unroll
        for (int j = 0; j < 16; j++) op[j] = sp[j];
    }
}

// ---------------- RWKV scan: m-split x2, chunked cp.async + shuffle ----------------
constexpr int SCH = 16;
__global__ void __launch_bounds__(256)
scan_k(const float* __restrict__ rr, const float* __restrict__ kk,
       const float* __restrict__ vv, const float* __restrict__ td,
       const float* __restrict__ tf, float* __restrict__ yy) {
    __shared__ __align__(16) float rs[2][SCH * 64];
    __shared__ __align__(16) float ks[2][SCH * 64];
    __shared__ __align__(16) float vs[2][SCH * 64];
    int bh = blockIdx.x >> 1;
    int mh = blockIdx.x & 1;
    int h = bh & (H_ - 1);
    int tid = threadIdx.x;
    int m = tid >> 3, ns = tid & 7;
    size_t base = (size_t)bh * L_ * N_;

    float S[8], w[8], uk[8];
    #pragma unroll
    for (int i = 0; i < 8; i++) {
        int n = ns * 8 + i;
        w[i] = expf(-expf(td[h * N_ + n]));
        uk[i] = tf[h * N_ + n];
        S[i] = 0.f;
    }

    uint32_t sr = smem_u32(rs), sk = smem_u32(ks), sv = smem_u32(vs);
    const int NCH = L_ / SCH;
    uint32_t toff = (uint32_t)tid * 16;

    cp16(sr + toff, rr + base + tid * 4);
    cp16(sk + toff, kk + base + tid * 4);
    cp16(sv + toff, vv + base + tid * 4);
    asm volatile("cp.async.commit_group;");
    asm volatile("cp.async.wait_group 0;");
    __syncthreads();

    int gm = mh * 32 + m;
    for (int ch = 0; ch < NCH; ch++) {
        int q = ch & 1;
        if (ch + 1 < NCH) {
            uint32_t dst = (uint32_t)((q ^ 1) * SCH * 64 * 4) + toff;
            size_t gof = base + (size_t)(ch + 1) * SCH * 64 + tid * 4;
            cp16(sr + dst, rr + gof);
            cp16(sk + dst, kk + gof);
            cp16(sv + dst, vv + gof);
            asm volatile("cp.async.commit_group;");
        }
        const float* rb = rs[q];
        const float* kb = ks[q];
        const float* vb = vs[q];
        size_t yof = base + (size_t)ch * SCH * 64 + gm;
        #pragma unroll 4
        for (int s = 0; s < SCH; s++) {
            const float* rp = rb + s * 64 + ns * 8;
            const float* kp = kb + s * 64 + ns * 8;
            float vm = vb[s * 64 + gm];
            float t = 0.f, qq = 0.f;
            #pragma unroll
            for (int i = 0; i < 8; i += 4) {
                float4 r4 = *(const float4*)(rp + i);
                float4 k4 = *(const float4*)(kp + i);
                float rv[4] = {r4.x, r4.y, r4.z, r4.w};
                float kv[4] = {k4.x, k4.y, k4.z, k4.w};
                #pragma unroll
                for (int j = 0; j < 4; j++) {
                    int i2 = i + j;
                    t += rv[j] * S[i2];
                    qq += rv[j] * uk[i2] * kv[j];
                    S[i2] = w[i2] * S[i2] + kv[j] * vm;
                }
            }
            t  += __shfl_xor_sync(0xffffffffu, t, 1);
            t  += __shfl_xor_sync(0xffffffffu, t, 2);
            t  += __shfl_xor_sync(0xffffffffu, t, 4);
            qq += __shfl_xor_sync(0xffffffffu, qq, 1);
            qq += __shfl_xor_sync(0xffffffffu, qq, 2);
            qq += __shfl_xor_sync(0xffffffffu, qq, 4);
            if (ns == 0) yy[yof + (size_t)s * 64] = t + qq * vm;
        }
        if (ch + 1 < NCH) asm volatile("cp.async.wait_group 0;");
        __syncthreads();
    }
}

// ---------------- groupnorm * ln_x * gate -> fp16 (B,L,C) ----------------
__global__ void __launch_bounds__(256)
gnorm_k(const float* __restrict__ yy, const float* __restrict__ gate,
        const float* __restrict__ lnw, const float* __restrict__ lnb,
        __half* __restrict__ z) {
    int b = blockIdx.z, h = blockIdx.y, l0 = blockIdx.x * 64;
    __shared__ float tile[64][65];
    __shared__ float rs1[4][64], rs2[4][64];
    __shared__ float smean[64], sinv[64];
    int tid = threadIdx.x;
    size_t ybase = ((size_t)(b * H_ + h) * L_ + l0) * N_;

    #pragma unroll
    for (int i = 0; i < 16; i++) {
        int id = tid + i * 256;
        int row = id >> 6, col = id & 63;
        tile[col][row] = yy[ybase + (size_t)row * N_ + col];
    }
    __syncthreads();
    {
        int l = tid & 63, part = tid >> 6;
        float s1 = 0.f, s2 = 0.f;
        #pragma unroll
        for (int i = 0; i < 16; i++) {
            float v = tile[part * 16 + i][l];
            s1 += v; s2 += v * v;
        }
        rs1[part][l] = s1; rs2[part][l] = s2;
    }
    __syncthreads();
    if (tid < 64) {
        float s1 = rs1[0][tid] + rs1[1][tid] + rs1[2][tid] + rs1[3][tid];
        float s2 = rs2[0][tid] + rs2[1][tid] + rs2[2][tid] + rs2[3][tid];
        float mean = s1 * (1.f / 64);
        float var = s2 * (1.f / 64) - mean * mean;
        smean[tid] = mean;
        sinv[tid] = rsqrtf(var + 1e-5f);
    }
    __syncthreads();

    int n = tid >> 2, lq = tid & 3;
    int c = h * 64 + n;
    float lw = lnw[c], lb = lnb[c];
    #pragma unroll
    for (int q = 0; q < 16; q++) {
        int l = lq * 16 + q;
        size_t rofs = ((size_t)b * L_ + l0 + l) * C_ + c;
        float v = ((tile[n][l] - smean[l]) * sinv[l] * lw + lb) * gate[rofs];
        z[rofs] = __float2half(v);
    }
}

// ---------------- residual + rms ----------------
__global__ void __launch_bounds__(128)
resid_rms_k(const float* __restrict__ img, const float* __restrict__ txt,
            const float* __restrict__ attn, const float* __restrict__ mod,
            const float* __restrict__ w2i, const float* __restrict__ w2t,
            float* __restrict__ img1, float* __restrict__ txt1,
            float* __restrict__ himg, float* __restrict__ htxt) {
    int b = blockIdx.y;
    int l = blockIdx.x * 128 + threadIdx.x;
    int s, li, Ls;
    const float* src; float* d1; float* dh; const float* rw;
    if (l < LI_) { s = 0; li = l;       Ls = LI_; src = img; d1 = img1; dh = himg; rw = w2i; }
    else         { s = 1; li = l - LI_; Ls = LT_; src = txt; d1 = txt1; dh = htxt; rw = w2t; }
    const float* mb = mod + (s * B_ + b) * 6 * C_;
    const float* ap = attn + (size_t)b * C_ * L_ + l;
    const float* sp = src + (size_t)b * C_ * Ls + li;
    float* p1 = d1 + (size_t)b * C_ * Ls + li;
    float* ph = dh + (size_t)b * C_ * Ls + li;
    float ss = 0.f;
    #pragma unroll 4
    for (int c = 0; c < C_; c++) {
        float v = sp[(size_t)c * Ls] + mb[2 * C_ + c] * ap[(size_t)c * L_];
        p1[(size_t)c * Ls] = v;
        ss += v * v;
    }
    float inv = rsqrtf(ss * (1.f / C_) + 1e-6f);
    #pragma unroll 4
    for (int c = 0; c < C_; c++) {
        float v = p1[(size_t)c * Ls];
        ph[(size_t)c * Ls] = v * inv * rw[c] * (1.f + mb[4 * C_ + c]) + mb[3 * C_ + c];
    }
}

// ---------------- host ----------------
static float* symaddr(const void* s) {
    void* p = nullptr;
    cudaGetSymbolAddress(&p, s);
    return (float*)p;
}
static __half* symaddrh(const void* s) {
    void* p = nullptr;
    cudaGetSymbolAddress(&p, s);
    return (__half*)p;
}

extern "C" void kernel_launch(void* const* d_in, const int* in_sizes, int n_in,
                              void* d_out, int out_size) {
    const float* img   = (const float*)d_in[0];
    const float* txt   = (const float*)d_in[1];
    const float* cond  = (const float*)d_in[2];
    const float* Wmi   = (const float*)d_in[3];
    const float* bmi   = (const float*)d_in[4];
    const float* Wmt   = (const float*)d_in[5];
    const float* bmt   = (const float*)d_in[6];
    const float* rmsi  = (const float*)d_in[7];
    const float* rmst  = (const float*)d_in[8];
    const float* rmsi2 = (const float*)d_in[9];
    const float* rmst2 = (const float*)d_in[10];
    const float* mur   = (const float*)d_in[11];
    const float* muk   = (const float*)d_in[12];
    const float* muv   = (const float*)d_in[13];
    const float* mug   = (const float*)d_in[14];
    const float* Wr    = (const float*)d_in[15];
    const float* Wk    = (const float*)d_in[16];
    const float* Wv    = (const float*)d_in[17];
    const float* Wg    = (const float*)d_in[18];
    const float* Wo    = (const float*)d_in[19];
    const float* td    = (const float*)d_in[20];
    const float* tf    = (const float*)d_in[21];
    const float* lnw   = (const float*)d_in[22];
    const float* lnb   = (const float*)d_in[23];
    const float* fi1   = (const float*)d_in[24];
    const float* fi2   = (const float*)d_in[25];
    const float* ft1   = (const float*)d_in[26];
    const float* ft2   = (const float*)d_in[27];

    float* p_mod   = symaddr(g_mod);
    float* p_inv   = symaddr(g_inv);
    float* p_gate  = symaddr(g_gate);
    float* p_r     = symaddr(g_r);
    float* p_k     = symaddr(g_k);
    float* p_v     = symaddr(g_v);
    float* p_y     = symaddr(g_y);
    float* p_attn  = symaddr(g_attn);
    float* p_img1  = symaddr(g_img1);
    float* p_txt1  = symaddr(g_txt1);
    float* p_himg  = symaddr(g_himg);
    float* p_htxt  = symaddr(g_htxt);

    __half* pArkvg = symaddrh(g_Arkvg);
    __half* pAwo   = symaddrh(g_Awo);
    __half* pAfi1  = symaddrh(g_Afi1);
    __half* pAfi2  = symaddrh(g_Afi2);
    __half* pAft1  = symaddrh(g_Aft1);
    __half* pAft2  = symaddrh(g_Aft2);
    __half* pBx4   = symaddrh(g_Bx4);
    __half* pBz    = symaddrh(g_Bz);
    __half* pBhi   = symaddrh(g_Bhi);
    __half* pBht   = symaddrh(g_Bht);
    __half* pBmi   = symaddrh(g_Bmi);
    __half* pBmt   = symaddrh(g_Bmt);

    float* out_img = (float*)d_out;
    float* out_txt = out_img + IMGSZ;

    cudaFuncSetAttribute(gemm_mma<0>, cudaFuncAttributeMaxDynamicSharedMemorySize, GSMEM);
    cudaFuncSetAttribute(gemm_mma<1>, cudaFuncAttributeMaxDynamicSharedMemorySize, GSMEM);
    cudaFuncSetAttribute(gemm_mma<2>, cudaFuncAttributeMaxDynamicSharedMemorySize, GSMEM);
    cudaFuncSetAttribute(gemm_mma<3>, cudaFuncAttributeMaxDynamicSharedMemorySize, GSMEM);

    // 0) fused modulation + rms sums
    prep_k<<<MOD_BLOCKS + RMS_BLOCKS, 256>>>(cond, Wmi, bmi, Wmt, bmt, img, txt,
                                             p_mod, p_inv);
    // 1) rkvg weight pack
    wpack4_k<<<(4 * 1024 * 1024) / 256, 256>>>(Wr, Wk, Wv, Wg, pArkvg);
    // 2) mixed inputs (B,L,C) x4 parts
    bxmix_k<<<dim3(L_ / 32, C_ / 32, B_), 256>>>(img, txt, rmsi, rmst, p_mod, p_inv,
                                                 mur, muk, muv, mug, pBx4);
    // 3) fused rkvg GEMM  (profiled launch)
    gemm_mma<1><<<dim3(L_ / 256, 4096 / 128, B_), 256, GSMEM>>>(
        pArkvg, pBx4, nullptr, nullptr, p_r, p_k, p_v, p_gate,
        nullptr, nullptr, 4096, 1024, L_);

    // remaining weight packs
    wsplit1_plain_k<<<(1024 * 1024) / 256, 256>>>(Wo,  pAwo,  (size_t)1024 * 1024);
    wsplit1_plain_k<<<(2048 * 1024) / 256, 256>>>(fi1, pAfi1, (size_t)2048 * 1024);
    wsplit1_plain_k<<<(1024 * 2048) / 256, 256>>>(fi2, pAfi2, (size_t)1024 * 2048);
    wsplit1_plain_k<<<(2048 * 1024) / 256, 256>>>(ft1, pAft1, (size_t)2048 * 1024);
    wsplit1_plain_k<<<(1024 * 2048) / 256, 256>>>(ft2, pAft2, (size_t)1024 * 2048);

    // scan (64 blocks: (b,h) x m-half)
    scan_k<<<B_ * H_ * 2, 256>>>(p_r, p_k, p_v, td, tf, p_y);

    // groupnorm * gate -> fp16 (B,L,C)
    gnorm_k<<<dim3(L_ / 64, H_, B_), 256>>>(p_y, p_gate, lnw, lnb, pBz);

    // Wo GEMM -> attn (B,C,L)
    gemm_mma<0><<<dim3(L_ / 256, C_ / 128, B_), 256, GSMEM>>>(
        pAwo, pBz, p_attn, nullptr, nullptr, nullptr, nullptr, nullptr,
        nullptr, nullptr, C_, 1024, L_);

    // residual + rms
    resid_rms_k<<<dim3(L_ / 128, B_), 128>>>(img, txt, p_attn, p_mod, rmsi2, rmst2,
                                             p_img1, p_txt1, p_himg, p_htxt);

    // FFN img
    asplit1_k<<<dim3(LI_ / 32, C_ / 32, B_), 256>>>(p_himg, pBhi, C_, LI_);
    gemm_mma<2><<<dim3(LI_ / 256, HID_ / 128, B_), 256, GSMEM>>>(
        pAfi1, pBhi, nullptr, pBmi, nullptr, nullptr, nullptr, nullptr,
        nullptr, nullptr, HID_, 1024, LI_);
    gemm_mma<3><<<dim3(LI_ / 256, C_ / 128, B_), 256, GSMEM>>>(
        pAfi2, pBmi, out_img, nullptr, nullptr, nullptr, nullptr, nullptr,
        p_img1, p_mod + 5 * C_, C_, 2048, LI_);

    // FFN txt
    asplit1_k<<<dim3(LT_ / 32, C_ / 32, B_), 256>>>(p_htxt, pBht, C_, LT_);
    gemm_mma<2><<<dim3(LT_ / 256, HID_ / 128, B_), 256, GSMEM>>>(
        pAft1, pBht, nullptr, pBmt, nullptr, nullptr, nullptr, nullptr,
        nullptr, nullptr, HID_, 1024, LT_);
    gemm_mma<3><<<dim3(LT_ / 256, C_ / 128, B_), 256, GSMEM>>>(
        pAft2, pBmt, out_txt, nullptr, nullptr, nullptr, nullptr, nullptr,
        p_txt1, p_mod + B_ * 6 * C_ + 5 * C_, C_, 2048, LT_);
}

// round 12
// speedup vs baseline: 1.4514x; 1.4514x over previous
#include <cuda_runtime.h>
#include <cuda_fp16.h>
#include <math.h>
#include <stdint.h>

constexpr int B_  = 2;
constexpr int C_  = 1024;
constexpr int H_  = 16;
constexpr int N_  = 64;
constexpr int LI_ = 4096;
constexpr int LT_ = 512;
constexpr int L_  = LI_ + LT_;   // 4608
constexpr int HID_ = 2048;

constexpr size_t XSZ   = (size_t)B_ * C_ * L_;
constexpr size_t IMGSZ = (size_t)B_ * C_ * LI_;
constexpr size_t TXTSZ = (size_t)B_ * C_ * LT_;

// ---------------- static scratch ----------------
__device__ float g_mod[2 * B_ * 6 * C_];
__device__ float g_ss [B_ * L_];                     // sum sq of raw img/txt
__device__ float g_ss2[B_ * L_];                     // sum sq of img1/txt1
__device__ float g_gate[XSZ];                        // silu(g) in (B,L,C)
__device__ float g_r[XSZ];                           // (B,H,L,N)
__device__ float g_k[XSZ];
__device__ float g_v[XSZ];
__device__ float g_y[XSZ];
__device__ float g_attn[XSZ];                        // (B,C,L)
__device__ float g_img1[IMGSZ];
__device__ float g_txt1[TXTSZ];

// fp16 GEMM operands
__device__ __half g_Arkvg[(size_t)4096 * 1024];      // [Wr;Wk;Wv;Wg]
__device__ __half g_Awo [(size_t)1024 * 1024];
__device__ __half g_Afi1[(size_t)2048 * 1024];
__device__ __half g_Afi2[(size_t)1024 * 2048];
__device__ __half g_Aft1[(size_t)2048 * 1024];
__device__ __half g_Aft2[(size_t)1024 * 2048];
__device__ __half g_Bx4[(size_t)4 * B_ * L_ * 1024]; // mixed inputs per part p
__device__ __half g_Bz [(size_t)B_ * L_  * 1024];
__device__ __half g_Bhi[(size_t)B_ * LI_ * 1024];
__device__ __half g_Bht[(size_t)B_ * LT_ * 1024];
__device__ __half g_Bmi[(size_t)B_ * LI_ * 2048];
__device__ __half g_Bmt[(size_t)B_ * LT_ * 2048];

// ---------------- helpers ----------------
__device__ __forceinline__ uint32_t smem_u32(const void* p) {
    uint32_t r;
    asm("{ .reg .u64 t; cvta.to.shared.u64 t, %1; cvt.u32.u64 %0, t; }" : "=r"(r) : "l"(p));
    return r;
}
__device__ __forceinline__ void cp16(uint32_t s, const void* g) {
    asm volatile("cp.async.cg.shared.global [%0], [%1], 16;" :: "r"(s), "l"(g));
}
__device__ __forceinline__ void ldsm4(uint32_t* r, uint32_t addr) {
    asm volatile("ldmatrix.sync.aligned.m8n8.x4.shared.b16 {%0,%1,%2,%3},[%4];"
                 : "=r"(r[0]), "=r"(r[1]), "=r"(r[2]), "=r"(r[3]) : "r"(addr));
}
__device__ __forceinline__ void mma16816(float* d, const uint32_t* a, const uint32_t* b) {
    asm volatile("mma.sync.aligned.m16n8k16.row.col.f32.f16.f16.f32 "
                 "{%0,%1,%2,%3},{%4,%5,%6,%7},{%8,%9},{%0,%1,%2,%3};"
                 : "+f"(d[0]), "+f"(d[1]), "+f"(d[2]), "+f"(d[3])
                 : "r"(a[0]), "r"(a[1]), "r"(a[2]), "r"(a[3]), "r"(b[0]), "r"(b[1]));
}
__device__ __forceinline__ float rms_inv(const float* ss, int idx) {
    return rsqrtf(ss[idx] * (1.f / C_) + 1e-6f);
}

// ---------------- prep: modulation (silu inline) + zero ss ----------------
constexpr int MOD_BLOCKS  = (2 * 6 * C_) / 8;    // 1536
constexpr int ZERO_BLOCKS = (2 * B_ * L_) / 256; // 72

__global__ void prep_k(const float* __restrict__ cond,
                       const float* __restrict__ Wimg, const float* __restrict__ bimg,
                       const float* __restrict__ Wtxt, const float* __restrict__ btxt,
                       float* __restrict__ modout, float* __restrict__ ss,
                       float* __restrict__ ss2) {
    if (blockIdx.x < MOD_BLOCKS) {
        int gw = (blockIdx.x * 256 + threadIdx.x) >> 5;
        int lane = threadIdx.x & 31;
        int s = gw / (6 * C_), o = gw % (6 * C_);
        const float* Wp = (s ? Wtxt : Wimg) + (size_t)o * C_;
        float a0 = 0.f, a1 = 0.f;
        for (int c = lane; c < C_; c += 32) {
            float wv = Wp[c];
            float c0 = cond[c], c1 = cond[C_ + c];
            a0 += wv * (c0 / (1.f + expf(-c0)));
            a1 += wv * (c1 / (1.f + expf(-c1)));
        }
        #pragma unroll
        for (int off = 16; off; off >>= 1) {
            a0 += __shfl_down_sync(0xffffffffu, a0, off);
            a1 += __shfl_down_sync(0xffffffffu, a1, off);
        }
        if (lane == 0) {
            float bb = (s ? btxt : bimg)[o];
            modout[(s * B_ + 0) * 6 * C_ + o] = a0 + bb;
            modout[(s * B_ + 1) * 6 * C_ + o] = a1 + bb;
        }
    } else {
        int gid = (blockIdx.x - MOD_BLOCKS) * 256 + threadIdx.x;
        if (gid < B_ * L_) ss[gid] = 0.f;
        else if (gid < 2 * B_ * L_) ss2[gid - B_ * L_] = 0.f;
    }
}

// ---------------- prep2: wpack4 + tiled sumsq of raw img/txt ----------------
constexpr int WPK_BLOCKS = (4 * 1024 * 1024) / 256;          // 16384
constexpr int SQ_BLOCKS  = B_ * (C_ / 32) * (L_ / 32);       // 9216

__global__ void prep2_k(const float* __restrict__ Wr, const float* __restrict__ Wk,
                        const float* __restrict__ Wv, const float* __restrict__ Wg,
                        const float* __restrict__ img, const float* __restrict__ txt,
                        __half* __restrict__ A, float* __restrict__ ss) {
    if (blockIdx.x < WPK_BLOCKS) {
        size_t idx = (size_t)blockIdx.x * 256 + threadIdx.x;
        int p = (int)(idx >> 20);
        size_t rest = idx & 0xFFFFF;
        const float* W = (p == 0) ? Wr : (p == 1) ? Wk : (p == 2) ? Wv : Wg;
        A[idx] = __float2half(W[rest]);
    } else {
        int t = blockIdx.x - WPK_BLOCKS;
        int b = t / ((C_ / 32) * (L_ / 32));
        int rem = t % ((C_ / 32) * (L_ / 32));
        int c0 = (rem / (L_ / 32)) * 32;
        int l0 = (rem % (L_ / 32)) * 32;
        int tx = threadIdx.x & 31, wy = threadIdx.x >> 5;
        const float* src; int Ls, li0;
        if (l0 < LI_) { src = img; Ls = LI_; li0 = l0; }
        else          { src = txt; Ls = LT_; li0 = l0 - LI_; }
        float p = 0.f;
        #pragma unroll
        for (int i = 0; i < 4; i++) {
            int c = c0 + wy + i * 8;
            float v = src[((size_t)b * C_ + c) * Ls + li0 + tx];
            p += v * v;
        }
        __shared__ float red[8][33];
        red[wy][tx] = p;
        __syncthreads();
        if (threadIdx.x < 32) {
            float sacc = 0.f;
            #pragma unroll
            for (int j = 0; j < 8; j++) sacc += red[j][threadIdx.x];
            atomicAdd(&ss[b * L_ + l0 + threadIdx.x], sacc);
        }
    }
}

// ---------------- Bx4 build: rms-modulate + mix + transpose ----------------
__global__ void __launch_bounds__(256)
bxmix_k(const float* __restrict__ img, const float* __restrict__ txt,
        const float* __restrict__ rmswi, const float* __restrict__ rmswt,
        const float* __restrict__ mod, const float* __restrict__ ss,
        const float* __restrict__ mur, const float* __restrict__ muk,
        const float* __restrict__ muv, const float* __restrict__ mug,
        __half* __restrict__ out) {
    __shared__ float tileM[32][35];
    int b = blockIdx.z, c0 = blockIdx.y * 32, l0 = blockIdx.x * 32;
    int tx = threadIdx.x & 31, wy = threadIdx.x >> 5;
    int s0 = (l0 < LI_) ? 0 : 1;
    const float* src0 = s0 ? txt : img;
    int Ls0 = s0 ? LT_ : LI_;
    int li0 = s0 ? l0 - LI_ : l0;
    const float* mb0 = mod + (s0 * B_ + b) * 6 * C_;
    const float* rw0 = s0 ? rmswt : rmswi;
    float ivl = rms_inv(ss, b * L_ + l0 + tx);
    #pragma unroll
    for (int i = 0; i < 4; i++) {
        int c = wy + i * 8;
        int cg = c0 + c;
        float raw = src0[((size_t)b * C_ + cg) * Ls0 + li0 + tx];
        tileM[c][1 + tx] = raw * ivl * rw0[cg] * (1.f + mb0[C_ + cg]) + mb0[cg];
        if (tx == 0) {
            float pv = 0.f;
            if (l0 > 0) {
                int lm = l0 - 1;
                int sm = (lm < LI_) ? 0 : 1;
                const float* srcm = sm ? txt : img;
                int Lsm = sm ? LT_ : LI_;
                int lim = sm ? lm - LI_ : lm;
                const float* mbm = mod + (sm * B_ + b) * 6 * C_;
                const float* rwm = sm ? rmswt : rmswi;
                float rm = srcm[((size_t)b * C_ + cg) * Lsm + lim];
                pv = rm * rms_inv(ss, b * L_ + lm) * rwm[cg] * (1.f + mbm[C_ + cg]) + mbm[cg];
            }
            tileM[c][0] = pv;
        }
    }
    __syncthreads();
    int cg = c0 + tx;
    float m_r = mur[cg], m_k = muk[cg], m_v = muv[cg], m_g = mug[cg];
    const size_t PSTR = (size_t)B_ * L_ * 1024;
    #pragma unroll
    for (int i = 0; i < 4; i++) {
        int lrel = wy + i * 8;
        float vl = tileM[tx][1 + lrel];
        float vp = tileM[tx][lrel];
        float d = vp - vl;
        size_t base = ((size_t)b * L_ + l0 + lrel) * 1024 + cg;
        out[base]            = __float2half(vl + m_r * d);
        out[base + PSTR]     = __float2half(vl + m_k * d);
        out[base + 2 * PSTR] = __float2half(vl + m_v * d);
        out[base + 3 * PSTR] = __float2half(vl + m_g * d);
    }
}

// ---------------- mma.sync GEMM: 3-stage cp.async pipeline (R10 config) --------
constexpr int STG = 18432;            // 128 rows * 144B per operand stage
constexpr int GSMEM = 6 * STG;        // 3 stages x (A,B)

// MODE 0: plain fp32 (B,M,L). MODE 1: rkvg -> r/k/v (B,H,L,N) + gate(B,L,C)
// MODE 2: gelu -> fp16 (B,L,M). MODE 3: resid + gate -> fp32 (B,M,L)
template <int MODE>
__global__ void __launch_bounds__(256, 2)
gemm_mma(const __half* __restrict__ A, const __half* __restrict__ Bm,
         float* __restrict__ Y, __half* __restrict__ Yh,
         float* __restrict__ ro, float* __restrict__ ko, float* __restrict__ vo,
         float* __restrict__ go,
         const float* __restrict__ resid, const float* __restrict__ gmod,
         int M, int K, int Llen) {
    extern __shared__ __align__(16) char dsmem[];
    uint32_t sb = smem_u32(dsmem);
    int tid = threadIdx.x, lane = tid & 31, wid = tid >> 5;
    int wm = wid >> 2, wn = wid & 3;
    int b = blockIdx.z, l0 = blockIdx.x * 128, m0 = blockIdx.y * 128;
    const int NT = K >> 6;

    float acc[4][4][4] = {};
    const __half* Ag = A + (size_t)m0 * K;
    const __half* Bg;
    if (MODE == 1) {
        int part = m0 >> 10;
        Bg = Bm + (((size_t)(part * B_ + b)) * Llen + l0) * K;
    } else {
        Bg = Bm + ((size_t)b * Llen + l0) * K;
    }

    int r_ld = tid >> 1, seg = tid & 1;
    uint32_t soff = (uint32_t)(r_ld * 144 + seg * 64);
    const __half* Agr = Ag + (size_t)r_ld * K + seg * 32;
    const __half* Bgr = Bg + (size_t)r_ld * K + seg * 32;

    #pragma unroll
    for (int t = 0; t < 2; t++) {
        uint32_t ao = sb + t * STG + soff;
        uint32_t bo = sb + 3 * STG + t * STG + soff;
        #pragma unroll
        for (int j = 0; j < 4; j++) {
            cp16(ao + j * 16, Agr + t * 64 + j * 8);
            cp16(bo + j * 16, Bgr + t * 64 + j * 8);
        }
        asm volatile("cp.async.commit_group;");
    }

    for (int it = 0; it < NT; it++) {
        if (it + 1 < NT) asm volatile("cp.async.wait_group 1;");
        else             asm volatile("cp.async.wait_group 0;");
        __syncthreads();
        if (it + 2 < NT) {
            int st = (it + 2) % 3;
            int ka = (it + 2) * 64;
            uint32_t ao = sb + st * STG + soff;
            uint32_t bo = sb + 3 * STG + st * STG + soff;
            #pragma unroll
            for (int j = 0; j < 4; j++) {
                cp16(ao + j * 16, Agr + ka + j * 8);
                cp16(bo + j * 16, Bgr + ka + j * 8);
            }
            asm volatile("cp.async.commit_group;");
        }
        uint32_t baseA = sb + (it % 3) * STG;
        uint32_t baseB = sb + 3 * STG + (it % 3) * STG;
        #pragma unroll
        for (int kk = 0; kk < 4; kk++) {
            uint32_t a[4][4], bq[2][4];
            #pragma unroll
            for (int ma = 0; ma < 4; ma++)
                ldsm4(a[ma], baseA + (wm * 64 + ma * 16 + (lane & 15)) * 144
                              + kk * 32 + (lane >> 4) * 16);
            #pragma unroll
            for (int nb = 0; nb < 2; nb++)
                ldsm4(bq[nb], baseB + (wn * 32 + nb * 16 + (lane & 7) + ((lane >> 4) & 1) * 8) * 144
                               + kk * 32 + ((lane >> 3) & 1) * 16);
            #pragma unroll
            for (int ma = 0; ma < 4; ma++)
                #pragma unroll
                for (int na = 0; na < 4; na++)
                    mma16816(acc[ma][na], a[ma], &bq[na >> 1][(na & 1) * 2]);
        }
    }

    if (MODE == 0 || MODE == 3) {
        #pragma unroll
        for (int ma = 0; ma < 4; ma++) {
            #pragma unroll
            for (int hf = 0; hf < 2; hf++) {
                int m = m0 + wm * 64 + ma * 16 + (lane >> 2) + hf * 8;
                size_t ybase = ((size_t)b * M + m) * Llen;
                float gm = 0.f;
                if (MODE == 3) gm = gmod[b * 6 * C_ + m];
                #pragma unroll
                for (int na = 0; na < 4; na++) {
                    int col = l0 + wn * 32 + na * 8 + 2 * (lane & 3);
                    float v0 = acc[ma][na][hf * 2], v1 = acc[ma][na][hf * 2 + 1];
                    if (MODE == 3) {
                        float2 rr = *(const float2*)(resid + ybase + col);
                        v0 = rr.x + gm * v0;
                        v1 = rr.y + gm * v1;
                    }
                    *(float2*)(Y + ybase + col) = make_float2(v0, v1);
                }
            }
        }
    } else if (MODE == 1) {
        __syncthreads();
        float* st = (float*)dsmem;
        int part = m0 >> 10;
        int c0 = m0 & 1023;
        #pragma unroll
        for (int ma = 0; ma < 4; ma++)
            #pragma unroll
            for (int na = 0; na < 4; na++)
                #pragma unroll
                for (int e = 0; e < 4; e++) {
                    int hf = e >> 1, j = e & 1;
                    int m = wm * 64 + ma * 16 + (lane >> 2) + hf * 8;
                    int l = wn * 32 + na * 8 + 2 * (lane & 3) + j;
                    float v = acc[ma][na][hf * 2 + j];
                    if (part == 3) v = v / (1.f + expf(-v));
                    st[l * 132 + m] = v;
                }
        __syncthreads();
        int l = tid >> 1, sg = tid & 1;
        const float* sp = st + l * 132 + sg * 64;
        if (part < 3) {
            float* outb = (part == 0) ? ro : (part == 1) ? ko : vo;
            int c = c0 + sg * 64;
            float* op = outb + ((size_t)(b * H_ + (c >> 6)) * L_ + l0 + l) * 64;
            #pragma unroll
            for (int j = 0; j < 64; j += 4)
                *(float4*)(op + j) = *(const float4*)(sp + j);
        } else {
            float* op = go + ((size_t)b * L_ + l0 + l) * C_ + c0 + sg * 64;
            #pragma unroll
            for (int j = 0; j < 64; j += 4)
                *(float4*)(op + j) = *(const float4*)(sp + j);
        }
    } else { // MODE 2: gelu -> fp16 (B,L,M)
        __syncthreads();
        __half* st = (__half*)dsmem;
        #pragma unroll
        for (int ma = 0; ma < 4; ma++)
            #pragma unroll
            for (int na = 0; na < 4; na++)
                #pragma unroll
                for (int e = 0; e < 4; e++) {
                    int hf = e >> 1, j = e & 1;
                    int m = wm * 64 + ma * 16 + (lane >> 2) + hf * 8;
                    int l = wn * 32 + na * 8 + 2 * (lane & 3) + j;
                    float v = acc[ma][na][hf * 2 + j];
                    float t = 0.7978845608f * (v + 0.044715f * v * v * v);
                    v = 0.5f * v * (1.f + tanhf(t));
                    st[l * 136 + m] = __float2half(v);
                }
        __syncthreads();
        int l = tid >> 1, sg = tid & 1;
        const uint4* sp = (const uint4*)(st + l * 136 + sg * 64);
        uint4* op = (uint4*)(Yh + ((size_t)b * Llen + l0 + l) * M + m0 + sg * 64);
        #pragma unroll
        for (int j = 0; j < 8; j++) op[j] = sp[j];
    }
}

// ---------------- RWKV scan: m-split x2, chunked cp.async + shuffle ----------------
constexpr int SCH = 16;
__global__ void __launch_bounds__(256)
scan_k(const float* __restrict__ rr, const float* __restrict__ kk,
       const float* __restrict__ vv, const float* __restrict__ td,
       const float* __restrict__ tf, float* __restrict__ yy) {
    __shared__ __align__(16) float rs[2][SCH * 64];
    __shared__ __align__(16) float ks[2][SCH * 64];
    __shared__ __align__(16) float vs[2][SCH * 64];
    int bh = blockIdx.x >> 1;
    int mh = blockIdx.x & 1;
    int h = bh & (H_ - 1);
    int tid = threadIdx.x;
    int m = tid >> 3, ns = tid & 7;
    size_t base = (size_t)bh * L_ * N_;

    float S[8], w[8], uk[8];
    #pragma unroll
    for (int i = 0; i < 8; i++) {
        int n = ns * 8 + i;
        w[i] = expf(-expf(td[h * N_ + n]));
        uk[i] = tf[h * N_ + n];
        S[i] = 0.f;
    }

    uint32_t sr = smem_u32(rs), sk = smem_u32(ks), sv = smem_u32(vs);
    const int NCH = L_ / SCH;
    uint32_t toff = (uint32_t)tid * 16;

    cp16(sr + toff, rr + base + tid * 4);
    cp16(sk + toff, kk + base + tid * 4);
    cp16(sv + toff, vv + base + tid * 4);
    asm volatile("cp.async.commit_group;");
    asm volatile("cp.async.wait_group 0;");
    __syncthreads();

    int gm = mh * 32 + m;
    for (int ch = 0; ch < NCH; ch++) {
        int q = ch & 1;
        if (ch + 1 < NCH) {
            uint32_t dst = (uint32_t)((q ^ 1) * SCH * 64 * 4) + toff;
            size_t gof = base + (size_t)(ch + 1) * SCH * 64 + tid * 4;
            cp16(sr + dst, rr + gof);
            cp16(sk + dst, kk + gof);
            cp16(sv + dst, vv + gof);
            asm volatile("cp.async.commit_group;");
        }
        const float* rb = rs[q];
        const float* kb = ks[q];
        const float* vb = vs[q];
        size_t yof = base + (size_t)ch * SCH * 64 + gm;
        #pragma unroll 4
        for (int s = 0; s < SCH; s++) {
            const float* rp = rb + s * 64 + ns * 8;
            const float* kp = kb + s * 64 + ns * 8;
            float vm = vb[s * 64 + gm];
            float t = 0.f, qq = 0.f;
            #pragma unroll
            for (int i = 0; i < 8; i += 4) {
                float4 r4 = *(const float4*)(rp + i);
                float4 k4 = *(const float4*)(kp + i);
                float rv[4] = {r4.x, r4.y, r4.z, r4.w};
                float kv[4] = {k4.x, k4.y, k4.z, k4.w};
                #pragma unroll
                for (int j = 0; j < 4; j++) {
                    int i2 = i + j;
                    t += rv[j] * S[i2];
                    qq += rv[j] * uk[i2] * kv[j];
                    S[i2] = w[i2] * S[i2] + kv[j] * vm;
                }
            }
            t  += __shfl_xor_sync(0xffffffffu, t, 1);
            t  += __shfl_xor_sync(0xffffffffu, t, 2);
            t  += __shfl_xor_sync(0xffffffffu, t, 4);
            qq += __shfl_xor_sync(0xffffffffu, qq, 1);
            qq += __shfl_xor_sync(0xffffffffu, qq, 2);
            qq += __shfl_xor_sync(0xffffffffu, qq, 4);
            if (ns == 0) yy[yof + (size_t)s * 64] = t + qq * vm;
        }
        if (ch + 1 < NCH) asm volatile("cp.async.wait_group 0;");
        __syncthreads();
    }
}

// ---------------- groupnorm * ln_x * gate -> fp16 (B,L,C) ----------------
__global__ void __launch_bounds__(256)
gnorm_k(const float* __restrict__ yy, const float* __restrict__ gate,
        const float* __restrict__ lnw, const float* __restrict__ lnb,
        __half* __restrict__ z) {
    int b = blockIdx.z, h = blockIdx.y, l0 = blockIdx.x * 64;
    __shared__ float tile[64][65];
    __shared__ float rs1[4][64], rs2[4][64];
    __shared__ float smean[64], sinv[64];
    int tid = threadIdx.x;
    size_t ybase = ((size_t)(b * H_ + h) * L_ + l0) * N_;

    #pragma unroll
    for (int i = 0; i < 16; i++) {
        int id = tid + i * 256;
        int row = id >> 6, col = id & 63;
        tile[col][row] = yy[ybase + (size_t)row * N_ + col];
    }
    __syncthreads();
    {
        int l = tid & 63, part = tid >> 6;
        float s1 = 0.f, s2 = 0.f;
        #pragma unroll
        for (int i = 0; i < 16; i++) {
            float v = tile[part * 16 + i][l];
            s1 += v; s2 += v * v;
        }
        rs1[part][l] = s1; rs2[part][l] = s2;
    }
    __syncthreads();
    if (tid < 64) {
        float s1 = rs1[0][tid] + rs1[1][tid] + rs1[2][tid] + rs1[3][tid];
        float s2 = rs2[0][tid] + rs2[1][tid] + rs2[2][tid] + rs2[3][tid];
        float mean = s1 * (1.f / 64);
        float var = s2 * (1.f / 64) - mean * mean;
        smean[tid] = mean;
        sinv[tid] = rsqrtf(var + 1e-5f);
    }
    __syncthreads();

    int n = tid >> 2, lq = tid & 3;
    int c = h * 64 + n;
    float lw = lnw[c], lb = lnb[c];
    #pragma unroll
    for (int q = 0; q < 16; q++) {
        int l = lq * 16 + q;
        size_t rofs = ((size_t)b * L_ + l0 + l) * C_ + c;
        float v = ((tile[n][l] - smean[l]) * sinv[l] * lw + lb) * gate[rofs];
        z[rofs] = __float2half(v);
    }
}

// ---------------- resid1: img1 = img + g1*attn, tiled + ss2 atomics ----------------
__global__ void __launch_bounds__(256)
resid1_k(const float* __restrict__ img, const float* __restrict__ txt,
         const float* __restrict__ attn, const float* __restrict__ mod,
         float* __restrict__ img1, float* __restrict__ txt1,
         float* __restrict__ ss2) {
    int b = blockIdx.z, c0 = blockIdx.y * 32, l0 = blockIdx.x * 32;
    int tx = threadIdx.x & 31, wy = threadIdx.x >> 5;
    int s0 = (l0 < LI_) ? 0 : 1;
    const float* src = s0 ? txt : img;
    float* dst = s0 ? txt1 : img1;
    int Ls = s0 ? LT_ : LI_;
    int li0 = s0 ? l0 - LI_ : l0;
    const float* mb = mod + (s0 * B_ + b) * 6 * C_;
    float p = 0.f;
    #pragma unroll
    for (int i = 0; i < 4; i++) {
        int c = c0 + wy + i * 8;
        size_t so = ((size_t)b * C_ + c) * Ls + li0 + tx;
        float v = src[so] + mb[2 * C_ + c] * attn[((size_t)b * C_ + c) * L_ + l0 + tx];
        dst[so] = v;
        p += v * v;
    }
    __shared__ float red[8][33];
    red[wy][tx] = p;
    __syncthreads();
    if (threadIdx.x < 32) {
        float sacc = 0.f;
        #pragma unroll
        for (int j = 0; j < 8; j++) sacc += red[j][threadIdx.x];
        atomicAdd(&ss2[b * L_ + l0 + threadIdx.x], sacc);
    }
}

// ---------------- hbuild: rms2-modulate img1 -> fp16 (B,L,C) transposed -------
__global__ void __launch_bounds__(256)
hbuild_k(const float* __restrict__ img1, const float* __restrict__ txt1,
         const float* __restrict__ rmsi2, const float* __restrict__ rmst2,
         const float* __restrict__ mod, const float* __restrict__ ss2,
         __half* __restrict__ bhi, __half* __restrict__ bht) {
    __shared__ float tile[32][33];
    __shared__ float sinv[32];
    int b = blockIdx.z, c0 = blockIdx.y * 32, l0 = blockIdx.x * 32;
    int tx = threadIdx.x & 31, wy = threadIdx.x >> 5;
    int s0 = (l0 < LI_) ? 0 : 1;
    const float* src = s0 ? txt1 : img1;
    __half* outb = s0 ? bht : bhi;
    const float* rw = s0 ? rmst2 : rmsi2;
    int Ls = s0 ? LT_ : LI_;
    int li0 = s0 ? l0 - LI_ : l0;
    const float* mb = mod + (s0 * B_ + b) * 6 * C_;
    #pragma unroll
    for (int i = 0; i < 4; i++) {
        int c = wy + i * 8;
        tile[c][tx] = src[((size_t)b * C_ + c0 + c) * Ls + li0 + tx];
    }
    if (threadIdx.x < 32)
        sinv[threadIdx.x] = rms_inv(ss2, b * L_ + l0 + threadIdx.x);
    __syncthreads();
    int c = c0 + tx;
    float a = rw[c] * (1.f + mb[4 * C_ + c]);
    float sh = mb[3 * C_ + c];
    #pragma unroll
    for (int i = 0; i < 4; i++) {
        int l = wy + i * 8;
        float v = tile[tx][l] * sinv[l] * a + sh;
        outb[((size_t)b * Ls + li0 + l) * 1024 + c] = __float2half(v);
    }
}

// ---------------- host ----------------
static float* symaddr(const void* s) {
    void* p = nullptr;
    cudaGetSymbolAddress(&p, s);
    return (float*)p;
}
static __half* symaddrh(const void* s) {
    void* p = nullptr;
    cudaGetSymbolAddress(&p, s);
    return (__half*)p;
}

__global__ void wsplit1_plain_k(const float* __restrict__ W, __half* __restrict__ A,
                                size_t total) {
    size_t idx = (size_t)blockIdx.x * 256 + threadIdx.x;
    if (idx < total) A[idx] = __float2half(W[idx]);
}

extern "C" void kernel_launch(void* const* d_in, const int* in_sizes, int n_in,
                              void* d_out, int out_size) {
    const float* img   = (const float*)d_in[0];
    const float* txt   = (const float*)d_in[1];
    const float* cond  = (const float*)d_in[2];
    const float* Wmi   = (const float*)d_in[3];
    const float* bmi   = (const float*)d_in[4];
    const float* Wmt   = (const float*)d_in[5];
    const float* bmt   = (const float*)d_in[6];
    const float* rmsi  = (const float*)d_in[7];
    const float* rmst  = (const float*)d_in[8];
    const float* rmsi2 = (const float*)d_in[9];
    const float* rmst2 = (const float*)d_in[10];
    const float* mur   = (const float*)d_in[11];
    const float* muk   = (const float*)d_in[12];
    const float* muv   = (const float*)d_in[13];
    const float* mug   = (const float*)d_in[14];
    const float* Wr    = (const float*)d_in[15];
    const float* Wk    = (const float*)d_in[16];
    const float* Wv    = (const float*)d_in[17];
    const float* Wg    = (const float*)d_in[18];
    const float* Wo    = (const float*)d_in[19];
    const float* td    = (const float*)d_in[20];
    const float* tf    = (const float*)d_in[21];
    const float* lnw   = (const float*)d_in[22];
    const float* lnb   = (const float*)d_in[23];
    const float* fi1   = (const float*)d_in[24];
    const float* fi2   = (const float*)d_in[25];
    const float* ft1   = (const float*)d_in[26];
    const float* ft2   = (const float*)d_in[27];

    float* p_mod   = symaddr(g_mod);
    float* p_ss    = symaddr(g_ss);
    float* p_ss2   = symaddr(g_ss2);
    float* p_gate  = symaddr(g_gate);
    float* p_r     = symaddr(g_r);
    float* p_k     = symaddr(g_k);
    float* p_v     = symaddr(g_v);
    float* p_y     = symaddr(g_y);
    float* p_attn  = symaddr(g_attn);
    float* p_img1  = symaddr(g_img1);
    float* p_txt1  = symaddr(g_txt1);

    __half* pArkvg = symaddrh(g_Arkvg);
    __half* pAwo   = symaddrh(g_Awo);
    __half* pAfi1  = symaddrh(g_Afi1);
    __half* pAfi2  = symaddrh(g_Afi2);
    __half* pAft1  = symaddrh(g_Aft1);
    __half* pAft2  = symaddrh(g_Aft2);
    __half* pBx4   = symaddrh(g_Bx4);
    __half* pBz    = symaddrh(g_Bz);
    __half* pBhi   = symaddrh(g_Bhi);
    __half* pBht   = symaddrh(g_Bht);
    __half* pBmi   = symaddrh(g_Bmi);
    __half* pBmt   = symaddrh(g_Bmt);

    float* out_img = (float*)d_out;
    float* out_txt = out_img + IMGSZ;

    cudaFuncSetAttribute(gemm_mma<0>, cudaFuncAttributeMaxDynamicSharedMemorySize, GSMEM);
    cudaFuncSetAttribute(gemm_mma<1>, cudaFuncAttributeMaxDynamicSharedMemorySize, GSMEM);
    cudaFuncSetAttribute(gemm_mma<2>, cudaFuncAttributeMaxDynamicSharedMemorySize, GSMEM);
    cudaFuncSetAttribute(gemm_mma<3>, cudaFuncAttributeMaxDynamicSharedMemorySize, GSMEM);

    // 0) modulation + zero ss accumulators
    prep_k<<<MOD_BLOCKS + ZERO_BLOCKS, 256>>>(cond, Wmi, bmi, Wmt, bmt,
                                              p_mod, p_ss, p_ss2);
    // 1) rkvg weight pack + tiled sumsq of raw inputs
    prep2_k<<<WPK_BLOCKS + SQ_BLOCKS, 256>>>(Wr, Wk, Wv, Wg, img, txt, pArkvg, p_ss);
    // 2) mixed inputs (B,L,C) x4 parts (inline rsqrt)
    bxmix_k<<<dim3(L_ / 32, C_ / 32, B_), 256>>>(img, txt, rmsi, rmst, p_mod, p_ss,
                                                 mur, muk, muv, mug, pBx4);
    // 3) fused rkvg GEMM  (profiled launch)
    gemm_mma<1><<<dim3(L_ / 128, 4096 / 128, B_), 256, GSMEM>>>(
        pArkvg, pBx4, nullptr, nullptr, p_r, p_k, p_v, p_gate,
        nullptr, nullptr, 4096, 1024, L_);

    // remaining weight packs
    wsplit1_plain_k<<<(1024 * 1024) / 256, 256>>>(Wo,  pAwo,  (size_t)1024 * 1024);
    wsplit1_plain_k<<<(2048 * 1024) / 256, 256>>>(fi1, pAfi1, (size_t)2048 * 1024);
    wsplit1_plain_k<<<(1024 * 2048) / 256, 256>>>(fi2, pAfi2, (size_t)1024 * 2048);
    wsplit1_plain_k<<<(2048 * 1024) / 256, 256>>>(ft1, pAft1, (size_t)2048 * 1024);
    wsplit1_plain_k<<<(1024 * 2048) / 256, 256>>>(ft2, pAft2, (size_t)1024 * 2048);

    // scan (64 blocks: (b,h) x m-half)
    scan_k<<<B_ * H_ * 2, 256>>>(p_r, p_k, p_v, td, tf, p_y);

    // groupnorm * gate -> fp16 (B,L,C)
    gnorm_k<<<dim3(L_ / 64, H_, B_), 256>>>(p_y, p_gate, lnw, lnb, pBz);

    // Wo GEMM -> attn (B,C,L)
    gemm_mma<0><<<dim3(L_ / 128, C_ / 128, B_), 256, GSMEM>>>(
        pAwo, pBz, p_attn, nullptr, nullptr, nullptr, nullptr, nullptr,
        nullptr, nullptr, C_, 1024, L_);

    // residual (tiled) + rms2 sums
    resid1_k<<<dim3(L_ / 32, C_ / 32, B_), 256>>>(img, txt, p_attn, p_mod,
                                                  p_img1, p_txt1, p_ss2);
    // h build -> fp16 B operands for ffn1 (both streams)
    hbuild_k<<<dim3(L_ / 32, C_ / 32, B_), 256>>>(p_img1, p_txt1, rmsi2, rmst2,
                                                  p_mod, p_ss2, pBhi, pBht);

    // FFN img
    gemm_mma<2><<<dim3(LI_ / 128, HID_ / 128, B_), 256, GSMEM>>>(
        pAfi1, pBhi, nullptr, pBmi, nullptr, nullptr, nullptr, nullptr,
        nullptr, nullptr, HID_, 1024, LI_);
    gemm_mma<3><<<dim3(LI_ / 128, C_ / 128, B_), 256, GSMEM>>>(
        pAfi2, pBmi, out_img, nullptr, nullptr, nullptr, nullptr, nullptr,
        p_img1, p_mod + 5 * C_, C_, 2048, LI_);

    // FFN txt
    gemm_mma<2><<<dim3(LT_ / 128, HID_ / 128, B_), 256, GSMEM>>>(
        pAft1, pBht, nullptr, pBmt, nullptr, nullptr, nullptr, nullptr,
        nullptr, nullptr, HID_, 1024, LT_);
    gemm_mma<3><<<dim3(LT_ / 128, C_ / 128, B_), 256, GSMEM>>>(
        pAft2, pBmt, out_txt, nullptr, nullptr, nullptr, nullptr, nullptr,
        p_txt1, p_mod + B_ * 6 * C_ + 5 * C_, C_, 2048, LT_);
}

// round 13
// speedup vs baseline: 1.7466x; 1.2034x over previous
#include <cuda_runtime.h>
#include <cuda_fp16.h>
#include <math.h>
#include <stdint.h>

constexpr int B_  = 2;
constexpr int C_  = 1024;
constexpr int H_  = 16;
constexpr int N_  = 64;
constexpr int LI_ = 4096;
constexpr int LT_ = 512;
constexpr int L_  = LI_ + LT_;   // 4608
constexpr int HID_ = 2048;

constexpr size_t XSZ   = (size_t)B_ * C_ * L_;
constexpr size_t IMGSZ = (size_t)B_ * C_ * LI_;
constexpr size_t TXTSZ = (size_t)B_ * C_ * LT_;

// ---------------- static scratch ----------------
__device__ float g_mod[2 * B_ * 6 * C_];
__device__ float g_ss [B_ * L_];
__device__ float g_ss2[B_ * L_];
__device__ float g_gate[XSZ];                        // silu(g) in (B,L,C)
__device__ float g_r[XSZ];                           // (B,H,L,N)
__device__ float g_k[XSZ];
__device__ float g_v[XSZ];
__device__ float g_y[XSZ];
__device__ float g_attn[XSZ];                        // (B,C,L)
__device__ float g_img1[IMGSZ];
__device__ float g_txt1[TXTSZ];

// fp16 GEMM operands
__device__ __half g_Arkvg[(size_t)4096 * 1024];      // [Wr;Wk;Wv;Wg]
__device__ __half g_Awo [(size_t)1024 * 1024];
__device__ __half g_Afi1[(size_t)2048 * 1024];
__device__ __half g_Afi2[(size_t)1024 * 2048];
__device__ __half g_Aft1[(size_t)2048 * 1024];
__device__ __half g_Aft2[(size_t)1024 * 2048];
__device__ __half g_Bx4[(size_t)4 * B_ * L_ * 1024];
__device__ __half g_Bz [(size_t)B_ * L_  * 1024];
__device__ __half g_Bh [(size_t)B_ * L_  * 1024];    // merged ffn1 B operand
__device__ __half g_Bm [(size_t)B_ * L_  * 2048];    // merged ffn1 out / ffn2 B

// ---------------- helpers ----------------
__device__ __forceinline__ uint32_t smem_u32(const void* p) {
    uint32_t r;
    asm("{ .reg .u64 t; cvta.to.shared.u64 t, %1; cvt.u32.u64 %0, t; }" : "=r"(r) : "l"(p));
    return r;
}
__device__ __forceinline__ void cp16(uint32_t s, const void* g) {
    asm volatile("cp.async.cg.shared.global [%0], [%1], 16;" :: "r"(s), "l"(g));
}
__device__ __forceinline__ void ldsm4(uint32_t* r, uint32_t addr) {
    asm volatile("ldmatrix.sync.aligned.m8n8.x4.shared.b16 {%0,%1,%2,%3},[%4];"
                 : "=r"(r[0]), "=r"(r[1]), "=r"(r[2]), "=r"(r[3]) : "r"(addr));
}
__device__ __forceinline__ void mma16816(float* d, const uint32_t* a, const uint32_t* b) {
    asm volatile("mma.sync.aligned.m16n8k16.row.col.f32.f16.f16.f32 "
                 "{%0,%1,%2,%3},{%4,%5,%6,%7},{%8,%9},{%0,%1,%2,%3};"
                 : "+f"(d[0]), "+f"(d[1]), "+f"(d[2]), "+f"(d[3])
                 : "r"(a[0]), "r"(a[1]), "r"(a[2]), "r"(a[3]), "r"(b[0]), "r"(b[1]));
}
__device__ __forceinline__ float rms_inv(const float* ss, int idx) {
    return rsqrtf(ss[idx] * (1.f / C_) + 1e-6f);
}

// ---------------- prep: modulation (silu inline) + zero ss ----------------
constexpr int MOD_BLOCKS  = (2 * 6 * C_) / 8;    // 1536
constexpr int ZERO_BLOCKS = (2 * B_ * L_) / 256; // 72

__global__ void prep_k(const float* __restrict__ cond,
                       const float* __restrict__ Wimg, const float* __restrict__ bimg,
                       const float* __restrict__ Wtxt, const float* __restrict__ btxt,
                       float* __restrict__ modout, float* __restrict__ ss,
                       float* __restrict__ ss2) {
    if (blockIdx.x < MOD_BLOCKS) {
        int gw = (blockIdx.x * 256 + threadIdx.x) >> 5;
        int lane = threadIdx.x & 31;
        int s = gw / (6 * C_), o = gw % (6 * C_);
        const float* Wp = (s ? Wtxt : Wimg) + (size_t)o * C_;
        float a0 = 0.f, a1 = 0.f;
        for (int c = lane; c < C_; c += 32) {
            float wv = Wp[c];
            float c0 = cond[c], c1 = cond[C_ + c];
            a0 += wv * (c0 / (1.f + expf(-c0)));
            a1 += wv * (c1 / (1.f + expf(-c1)));
        }
        #pragma unroll
        for (int off = 16; off; off >>= 1) {
            a0 += __shfl_down_sync(0xffffffffu, a0, off);
            a1 += __shfl_down_sync(0xffffffffu, a1, off);
        }
        if (lane == 0) {
            float bb = (s ? btxt : bimg)[o];
            modout[(s * B_ + 0) * 6 * C_ + o] = a0 + bb;
            modout[(s * B_ + 1) * 6 * C_ + o] = a1 + bb;
        }
    } else {
        int gid = (blockIdx.x - MOD_BLOCKS) * 256 + threadIdx.x;
        if (gid < B_ * L_) ss[gid] = 0.f;
        else if (gid < 2 * B_ * L_) ss2[gid - B_ * L_] = 0.f;
    }
}

// ---------------- prep2: wpack4 + tiled sumsq of raw img/txt ----------------
constexpr int WPK_BLOCKS = (4 * 1024 * 1024) / 256;          // 16384
constexpr int SQ_BLOCKS  = B_ * (C_ / 32) * (L_ / 32);       // 9216

__global__ void prep2_k(const float* __restrict__ Wr, const float* __restrict__ Wk,
                        const float* __restrict__ Wv, const float* __restrict__ Wg,
                        const float* __restrict__ img, const float* __restrict__ txt,
                        __half* __restrict__ A, float* __restrict__ ss) {
    if (blockIdx.x < WPK_BLOCKS) {
        size_t idx = (size_t)blockIdx.x * 256 + threadIdx.x;
        int p = (int)(idx >> 20);
        size_t rest = idx & 0xFFFFF;
        const float* W = (p == 0) ? Wr : (p == 1) ? Wk : (p == 2) ? Wv : Wg;
        A[idx] = __float2half(W[rest]);
    } else {
        int t = blockIdx.x - WPK_BLOCKS;
        int b = t / ((C_ / 32) * (L_ / 32));
        int rem = t % ((C_ / 32) * (L_ / 32));
        int c0 = (rem / (L_ / 32)) * 32;
        int l0 = (rem % (L_ / 32)) * 32;
        int tx = threadIdx.x & 31, wy = threadIdx.x >> 5;
        const float* src; int Ls, li0;
        if (l0 < LI_) { src = img; Ls = LI_; li0 = l0; }
        else          { src = txt; Ls = LT_; li0 = l0 - LI_; }
        float p = 0.f;
        #pragma unroll
        for (int i = 0; i < 4; i++) {
            int c = c0 + wy + i * 8;
            float v = src[((size_t)b * C_ + c) * Ls + li0 + tx];
            p += v * v;
        }
        __shared__ float red[8][33];
        red[wy][tx] = p;
        __syncthreads();
        if (threadIdx.x < 32) {
            float sacc = 0.f;
            #pragma unroll
            for (int j = 0; j < 8; j++) sacc += red[j][threadIdx.x];
            atomicAdd(&ss[b * L_ + l0 + threadIdx.x], sacc);
        }
    }
}

// ---------------- merged plain weight packs ----------------
constexpr size_t WO_E  = (size_t)1024 * 1024;
constexpr size_t FI1_E = (size_t)2048 * 1024;
constexpr size_t FI2_E = (size_t)1024 * 2048;
constexpr size_t FT1_E = (size_t)2048 * 1024;
constexpr size_t WPALL = WO_E + FI1_E + FI2_E + FT1_E + FI2_E;   // 9M

__global__ void wpackall_k(const float* __restrict__ Wo,  const float* __restrict__ fi1,
                           const float* __restrict__ fi2, const float* __restrict__ ft1,
                           const float* __restrict__ ft2,
                           __half* __restrict__ Awo,  __half* __restrict__ Afi1,
                           __half* __restrict__ Afi2, __half* __restrict__ Aft1,
                           __half* __restrict__ Aft2) {
    size_t idx = (size_t)blockIdx.x * 256 + threadIdx.x;
    if (idx >= WPALL) return;
    if (idx < WO_E) { Awo[idx] = __float2half(Wo[idx]); return; }
    idx -= WO_E;
    if (idx < FI1_E) { Afi1[idx] = __float2half(fi1[idx]); return; }
    idx -= FI1_E;
    if (idx < FI2_E) { Afi2[idx] = __float2half(fi2[idx]); return; }
    idx -= FI2_E;
    if (idx < FT1_E) { Aft1[idx] = __float2half(ft1[idx]); return; }
    idx -= FT1_E;
    Aft2[idx] = __float2half(ft2[idx]);
}

// ---------------- Bx4 build: rms-modulate + mix + transpose ----------------
__global__ void __launch_bounds__(256)
bxmix_k(const float* __restrict__ img, const float* __restrict__ txt,
        const float* __restrict__ rmswi, const float* __restrict__ rmswt,
        const float* __restrict__ mod, const float* __restrict__ ss,
        const float* __restrict__ mur, const float* __restrict__ muk,
        const float* __restrict__ muv, const float* __restrict__ mug,
        __half* __restrict__ out) {
    __shared__ float tileM[32][35];
    int b = blockIdx.z, c0 = blockIdx.y * 32, l0 = blockIdx.x * 32;
    int tx = threadIdx.x & 31, wy = threadIdx.x >> 5;
    int s0 = (l0 < LI_) ? 0 : 1;
    const float* src0 = s0 ? txt : img;
    int Ls0 = s0 ? LT_ : LI_;
    int li0 = s0 ? l0 - LI_ : l0;
    const float* mb0 = mod + (s0 * B_ + b) * 6 * C_;
    const float* rw0 = s0 ? rmswt : rmswi;
    float ivl = rms_inv(ss, b * L_ + l0 + tx);
    #pragma unroll
    for (int i = 0; i < 4; i++) {
        int c = wy + i * 8;
        int cg = c0 + c;
        float raw = src0[((size_t)b * C_ + cg) * Ls0 + li0 + tx];
        tileM[c][1 + tx] = raw * ivl * rw0[cg] * (1.f + mb0[C_ + cg]) + mb0[cg];
        if (tx == 0) {
            float pv = 0.f;
            if (l0 > 0) {
                int lm = l0 - 1;
                int sm = (lm < LI_) ? 0 : 1;
                const float* srcm = sm ? txt : img;
                int Lsm = sm ? LT_ : LI_;
                int lim = sm ? lm - LI_ : lm;
                const float* mbm = mod + (sm * B_ + b) * 6 * C_;
                const float* rwm = sm ? rmswt : rmswi;
                float rm = srcm[((size_t)b * C_ + cg) * Lsm + lim];
                pv = rm * rms_inv(ss, b * L_ + lm) * rwm[cg] * (1.f + mbm[C_ + cg]) + mbm[cg];
            }
            tileM[c][0] = pv;
        }
    }
    __syncthreads();
    int cg = c0 + tx;
    float m_r = mur[cg], m_k = muk[cg], m_v = muv[cg], m_g = mug[cg];
    const size_t PSTR = (size_t)B_ * L_ * 1024;
    #pragma unroll
    for (int i = 0; i < 4; i++) {
        int lrel = wy + i * 8;
        float vl = tileM[tx][1 + lrel];
        float vp = tileM[tx][lrel];
        float d = vp - vl;
        size_t base = ((size_t)b * L_ + l0 + lrel) * 1024 + cg;
        out[base]            = __float2half(vl + m_r * d);
        out[base + PSTR]     = __float2half(vl + m_k * d);
        out[base + 2 * PSTR] = __float2half(vl + m_v * d);
        out[base + 3 * PSTR] = __float2half(vl + m_g * d);
    }
}

// ---------------- mma.sync GEMM: 3-stage cp.async pipeline (R10 config) --------
constexpr int STG = 18432;            // 128 rows * 144B per operand stage
constexpr int GSMEM = 6 * STG;

// MODE 0: plain fp32 (B,M,L). MODE 1: rkvg -> r/k/v (B,H,L,N) + gate(B,L,C)
// MODE 2: gelu -> fp16 (B,L,M), A selected by l0 vs LSPLIT
// MODE 3: resid + gate -> fp32, A/Y/resid/gmod selected by l0 vs LSPLIT
template <int MODE>
__global__ void __launch_bounds__(256, 2)
gemm_mma(const __half* __restrict__ A, const __half* __restrict__ A2,
         const __half* __restrict__ Bm,
         float* __restrict__ Y, float* __restrict__ Y2, __half* __restrict__ Yh,
         float* __restrict__ ro, float* __restrict__ ko, float* __restrict__ vo,
         float* __restrict__ go,
         const float* __restrict__ resid, const float* __restrict__ resid2,
         const float* __restrict__ gmod, const float* __restrict__ gmod2,
         int M, int K, int Llen, int LSPLIT) {
    extern __shared__ __align__(16) char dsmem[];
    uint32_t sb = smem_u32(dsmem);
    int tid = threadIdx.x, lane = tid & 31, wid = tid >> 5;
    int wm = wid >> 2, wn = wid & 3;
    int b = blockIdx.z, l0 = blockIdx.x * 128, m0 = blockIdx.y * 128;
    const int NT = K >> 6;

    bool second = (MODE == 2 || MODE == 3) && (l0 >= LSPLIT);
    const __half* Asel = second ? A2 : A;

    float acc[4][4][4] = {};
    const __half* Ag = Asel + (size_t)m0 * K;
    const __half* Bg;
    if (MODE == 1) {
        int part = m0 >> 10;
        Bg = Bm + (((size_t)(part * B_ + b)) * Llen + l0) * K;
    } else {
        Bg = Bm + ((size_t)b * Llen + l0) * K;
    }

    int r_ld = tid >> 1, seg = tid & 1;
    uint32_t soff = (uint32_t)(r_ld * 144 + seg * 64);
    const __half* Agr = Ag + (size_t)r_ld * K + seg * 32;
    const __half* Bgr = Bg + (size_t)r_ld * K + seg * 32;

    #pragma unroll
    for (int t = 0; t < 2; t++) {
        uint32_t ao = sb + t * STG + soff;
        uint32_t bo = sb + 3 * STG + t * STG + soff;
        #pragma unroll
        for (int j = 0; j < 4; j++) {
            cp16(ao + j * 16, Agr + t * 64 + j * 8);
            cp16(bo + j * 16, Bgr + t * 64 + j * 8);
        }
        asm volatile("cp.async.commit_group;");
    }

    for (int it = 0; it < NT; it++) {
        if (it + 1 < NT) asm volatile("cp.async.wait_group 1;");
        else             asm volatile("cp.async.wait_group 0;");
        __syncthreads();
        if (it + 2 < NT) {
            int st = (it + 2) % 3;
            int ka = (it + 2) * 64;
            uint32_t ao = sb + st * STG + soff;
            uint32_t bo = sb + 3 * STG + st * STG + soff;
            #pragma unroll
            for (int j = 0; j < 4; j++) {
                cp16(ao + j * 16, Agr + ka + j * 8);
                cp16(bo + j * 16, Bgr + ka + j * 8);
            }
            asm volatile("cp.async.commit_group;");
        }
        uint32_t baseA = sb + (it % 3) * STG;
        uint32_t baseB = sb + 3 * STG + (it % 3) * STG;
        #pragma unroll
        for (int kk = 0; kk < 4; kk++) {
            uint32_t a[4][4], bq[2][4];
            #pragma unroll
            for (int ma = 0; ma < 4; ma++)
                ldsm4(a[ma], baseA + (wm * 64 + ma * 16 + (lane & 15)) * 144
                              + kk * 32 + (lane >> 4) * 16);
            #pragma unroll
            for (int nb = 0; nb < 2; nb++)
                ldsm4(bq[nb], baseB + (wn * 32 + nb * 16 + (lane & 7) + ((lane >> 4) & 1) * 8) * 144
                               + kk * 32 + ((lane >> 3) & 1) * 16);
            #pragma unroll
            for (int ma = 0; ma < 4; ma++)
                #pragma unroll
                for (int na = 0; na < 4; na++)
                    mma16816(acc[ma][na], a[ma], &bq[na >> 1][(na & 1) * 2]);
        }
    }

    if (MODE == 0 || MODE == 3) {
        float* Yo = second ? Y2 : Y;
        const float* rs = second ? resid2 : resid;
        const float* gs = second ? gmod2 : gmod;
        int Lout = (MODE == 3) ? (second ? (Llen - LSPLIT) : LSPLIT) : Llen;
        int lb = second ? (l0 - LSPLIT) : l0;
        #pragma unroll
        for (int ma = 0; ma < 4; ma++) {
            #pragma unroll
            for (int hf = 0; hf < 2; hf++) {
                int m = m0 + wm * 64 + ma * 16 + (lane >> 2) + hf * 8;
                size_t ybase = ((size_t)b * M + m) * Lout;
                float gm = 0.f;
                if (MODE == 3) gm = gs[b * 6 * C_ + m];
                #pragma unroll
                for (int na = 0; na < 4; na++) {
                    int col = lb + wn * 32 + na * 8 + 2 * (lane & 3);
                    float v0 = acc[ma][na][hf * 2], v1 = acc[ma][na][hf * 2 + 1];
                    if (MODE == 3) {
                        float2 rr = *(const float2*)(rs + ybase + col);
                        v0 = rr.x + gm * v0;
                        v1 = rr.y + gm * v1;
                    }
                    *(float2*)(Yo + ybase + col) = make_float2(v0, v1);
                }
            }
        }
    } else if (MODE == 1) {
        __syncthreads();
        float* st = (float*)dsmem;
        int part = m0 >> 10;
        int c0 = m0 & 1023;
        #pragma unroll
        for (int ma = 0; ma < 4; ma++)
            #pragma unroll
            for (int na = 0; na < 4; na++)
                #pragma unroll
                for (int e = 0; e < 4; e++) {
                    int hf = e >> 1, j = e & 1;
                    int m = wm * 64 + ma * 16 + (lane >> 2) + hf * 8;
                    int l = wn * 32 + na * 8 + 2 * (lane & 3) + j;
                    float v = acc[ma][na][hf * 2 + j];
                    if (part == 3) v = v / (1.f + expf(-v));
                    st[l * 132 + m] = v;
                }
        __syncthreads();
        int l = tid >> 1, sg = tid & 1;
        const float* sp = st + l * 132 + sg * 64;
        if (part < 3) {
            float* outb = (part == 0) ? ro : (part == 1) ? ko : vo;
            int c = c0 + sg * 64;
            float* op = outb + ((size_t)(b * H_ + (c >> 6)) * L_ + l0 + l) * 64;
            #pragma unroll
            for (int j = 0; j < 64; j += 4)
                *(float4*)(op + j) = *(const float4*)(sp + j);
        } else {
            float* op = go + ((size_t)b * L_ + l0 + l) * C_ + c0 + sg * 64;
            #pragma unroll
            for (int j = 0; j < 64; j += 4)
                *(float4*)(op + j) = *(const float4*)(sp + j);
        }
    } else { // MODE 2: gelu -> fp16 (B,L,M)
        __syncthreads();
        __half* st = (__half*)dsmem;
        #pragma unroll
        for (int ma = 0; ma < 4; ma++)
            #pragma unroll
            for (int na = 0; na < 4; na++)
                #pragma unroll
                for (int e = 0; e < 4; e++) {
                    int hf = e >> 1, j = e & 1;
                    int m = wm * 64 + ma * 16 + (lane >> 2) + hf * 8;
                    int l = wn * 32 + na * 8 + 2 * (lane & 3) + j;
                    float v = acc[ma][na][hf * 2 + j];
                    float t = 0.7978845608f * (v + 0.044715f * v * v * v);
                    v = 0.5f * v * (1.f + tanhf(t));
                    st[l * 136 + m] = __float2half(v);
                }
        __syncthreads();
        int l = tid >> 1, sg = tid & 1;
        const uint4* sp = (const uint4*)(st + l * 136 + sg * 64);
        uint4* op = (uint4*)(Yh + ((size_t)b * Llen + l0 + l) * M + m0 + sg * 64);
        #pragma unroll
        for (int j = 0; j < 8; j++) op[j] = sp[j];
    }
}

// ---------------- RWKV scan: m-split x4, chunked cp.async + shuffle ----------------
constexpr int SCH = 16;
__global__ void __launch_bounds__(256)
scan_k(const float* __restrict__ rr, const float* __restrict__ kk,
       const float* __restrict__ vv, const float* __restrict__ td,
       const float* __restrict__ tf, float* __restrict__ yy) {
    __shared__ __align__(16) float rs[2][SCH * 64];
    __shared__ __align__(16) float ks[2][SCH * 64];
    __shared__ __align__(16) float vs[2][SCH * 64];
    int bh = blockIdx.x >> 2;
    int mh = blockIdx.x & 3;
    int h = bh & (H_ - 1);
    int tid = threadIdx.x;
    int m = tid >> 4, ns = tid & 15;
    size_t base = (size_t)bh * L_ * N_;

    float S[4], w[4], uk[4];
    #pragma unroll
    for (int i = 0; i < 4; i++) {
        int n = ns * 4 + i;
        w[i] = expf(-expf(td[h * N_ + n]));
        uk[i] = tf[h * N_ + n];
        S[i] = 0.f;
    }

    uint32_t sr = smem_u32(rs), sk = smem_u32(ks), sv = smem_u32(vs);
    const int NCH = L_ / SCH;
    uint32_t toff = (uint32_t)tid * 16;

    cp16(sr + toff, rr + base + tid * 4);
    cp16(sk + toff, kk + base + tid * 4);
    cp16(sv + toff, vv + base + tid * 4);
    asm volatile("cp.async.commit_group;");
    asm volatile("cp.async.wait_group 0;");
    __syncthreads();

    int gm = mh * 16 + m;
    for (int ch = 0; ch < NCH; ch++) {
        int q = ch & 1;
        if (ch + 1 < NCH) {
            uint32_t dst = (uint32_t)((q ^ 1) * SCH * 64 * 4) + toff;
            size_t gof = base + (size_t)(ch + 1) * SCH * 64 + tid * 4;
            cp16(sr + dst, rr + gof);
            cp16(sk + dst, kk + gof);
            cp16(sv + dst, vv + gof);
            asm volatile("cp.async.commit_group;");
        }
        const float* rb = rs[q];
        const float* kb = ks[q];
        const float* vb = vs[q];
        size_t yof = base + (size_t)ch * SCH * 64 + gm;
        #pragma unroll 4
        for (int s = 0; s < SCH; s++) {
            const float* rp = rb + s * 64 + ns * 4;
            const float* kp = kb + s * 64 + ns * 4;
            float vm = vb[s * 64 + gm];
            float t = 0.f, qq = 0.f;
            float4 r4 = *(const float4*)rp;
            float4 k4 = *(const float4*)kp;
            float rv[4] = {r4.x, r4.y, r4.z, r4.w};
            float kv[4] = {k4.x, k4.y, k4.z, k4.w};
            #pragma unroll
            for (int j = 0; j < 4; j++) {
                t += rv[j] * S[j];
                qq += rv[j] * uk[j] * kv[j];
                S[j] = w[j] * S[j] + kv[j] * vm;
            }
            t  += __shfl_xor_sync(0xffffffffu, t, 1);
            t  += __shfl_xor_sync(0xffffffffu, t, 2);
            t  += __shfl_xor_sync(0xffffffffu, t, 4);
            t  += __shfl_xor_sync(0xffffffffu, t, 8);
            qq += __shfl_xor_sync(0xffffffffu, qq, 1);
            qq += __shfl_xor_sync(0xffffffffu, qq, 2);
            qq += __shfl_xor_sync(0xffffffffu, qq, 4);
            qq += __shfl_xor_sync(0xffffffffu, qq, 8);
            if (ns == 0) yy[yof + (size_t)s * 64] = t + qq * vm;
        }
        if (ch + 1 < NCH) asm volatile("cp.async.wait_group 0;");
        __syncthreads();
    }
}

// ---------------- groupnorm * ln_x * gate -> fp16 (B,L,C) ----------------
__global__ void __launch_bounds__(256)
gnorm_k(const float* __restrict__ yy, const float* __restrict__ gate,
        const float* __restrict__ lnw, const float* __restrict__ lnb,
        __half* __restrict__ z) {
    int b = blockIdx.z, h = blockIdx.y, l0 = blockIdx.x * 64;
    __shared__ float tile[64][65];
    __shared__ float rs1[4][64], rs2[4][64];
    __shared__ float smean[64], sinv[64];
    int tid = threadIdx.x;
    size_t ybase = ((size_t)(b * H_ + h) * L_ + l0) * N_;

    #pragma unroll
    for (int i = 0; i < 16; i++) {
        int id = tid + i * 256;
        int row = id >> 6, col = id & 63;
        tile[col][row] = yy[ybase + (size_t)row * N_ + col];
    }
    __syncthreads();
    {
        int l = tid & 63, part = tid >> 6;
        float s1 = 0.f, s2 = 0.f;
        #pragma unroll
        for (int i = 0; i < 16; i++) {
            float v = tile[part * 16 + i][l];
            s1 += v; s2 += v * v;
        }
        rs1[part][l] = s1; rs2[part][l] = s2;
    }
    __syncthreads();
    if (tid < 64) {
        float s1 = rs1[0][tid] + rs1[1][tid] + rs1[2][tid] + rs1[3][tid];
        float s2 = rs2[0][tid] + rs2[1][tid] + rs2[2][tid] + rs2[3][tid];
        float mean = s1 * (1.f / 64);
        float var = s2 * (1.f / 64) - mean * mean;
        smean[tid] = mean;
        sinv[tid] = rsqrtf(var + 1e-5f);
    }
    __syncthreads();

    int n = tid >> 2, lq = tid & 3;
    int c = h * 64 + n;
    float lw = lnw[c], lb = lnb[c];
    #pragma unroll
    for (int q = 0; q < 16; q++) {
        int l = lq * 16 + q;
        size_t rofs = ((size_t)b * L_ + l0 + l) * C_ + c;
        float v = ((tile[n][l] - smean[l]) * sinv[l] * lw + lb) * gate[rofs];
        z[rofs] = __float2half(v);
    }
}

// ---------------- resid1: img1 = img + g1*attn, tiled + ss2 atomics ----------------
__global__ void __launch_bounds__(256)
resid1_k(const float* __restrict__ img, const float* __restrict__ txt,
         const float* __restrict__ attn, const float* __restrict__ mod,
         float* __restrict__ img1, float* __restrict__ txt1,
         float* __restrict__ ss2) {
    int b = blockIdx.z, c0 = blockIdx.y * 32, l0 = blockIdx.x * 32;
    int tx = threadIdx.x & 31, wy = threadIdx.x >> 5;
    int s0 = (l0 < LI_) ? 0 : 1;
    const float* src = s0 ? txt : img;
    float* dst = s0 ? txt1 : img1;
    int Ls = s0 ? LT_ : LI_;
    int li0 = s0 ? l0 - LI_ : l0;
    const float* mb = mod + (s0 * B_ + b) * 6 * C_;
    float p = 0.f;
    #pragma unroll
    for (int i = 0; i < 4; i++) {
        int c = c0 + wy + i * 8;
        size_t so = ((size_t)b * C_ + c) * Ls + li0 + tx;
        float v = src[so] + mb[2 * C_ + c] * attn[((size_t)b * C_ + c) * L_ + l0 + tx];
        dst[so] = v;
        p += v * v;
    }
    __shared__ float red[8][33];
    red[wy][tx] = p;
    __syncthreads();
    if (threadIdx.x < 32) {
        float sacc = 0.f;
        #pragma unroll
        for (int j = 0; j < 8; j++) sacc += red[j][threadIdx.x];
        atomicAdd(&ss2[b * L_ + l0 + threadIdx.x], sacc);
    }
}

// ---------------- hbuild: rms2-modulate img1/txt1 -> fp16 merged (B,L,C) ------
__global__ void __launch_bounds__(256)
hbuild_k(const float* __restrict__ img1, const float* __restrict__ txt1,
         const float* __restrict__ rmsi2, const float* __restrict__ rmst2,
         const float* __restrict__ mod, const float* __restrict__ ss2,
         __half* __restrict__ bh) {
    __shared__ float tile[32][33];
    __shared__ float sinv[32];
    int b = blockIdx.z, c0 = blockIdx.y * 32, l0 = blockIdx.x * 32;
    int tx = threadIdx.x & 31, wy = threadIdx.x >> 5;
    int s0 = (l0 < LI_) ? 0 : 1;
    const float* src = s0 ? txt1 : img1;
    const float* rw = s0 ? rmst2 : rmsi2;
    int Ls = s0 ? LT_ : LI_;
    int li0 = s0 ? l0 - LI_ : l0;
    const float* mb = mod + (s0 * B_ + b) * 6 * C_;
    #pragma unroll
    for (int i = 0; i < 4; i++) {
        int c = wy + i * 8;
        tile[c][tx] = src[((size_t)b * C_ + c0 + c) * Ls + li0 + tx];
    }
    if (threadIdx.x < 32)
        sinv[threadIdx.x] = rms_inv(ss2, b * L_ + l0 + threadIdx.x);
    __syncthreads();
    int c = c0 + tx;
    float a = rw[c] * (1.f + mb[4 * C_ + c]);
    float sh = mb[3 * C_ + c];
    #pragma unroll
    for (int i = 0; i < 4; i++) {
        int l = wy + i * 8;
        float v = tile[tx][l] * sinv[l] * a + sh;
        bh[((size_t)b * L_ + l0 + l) * 1024 + c] = __float2half(v);
    }
}

// ---------------- host ----------------
static float* symaddr(const void* s) {
    void* p = nullptr;
    cudaGetSymbolAddress(&p, s);
    return (float*)p;
}
static __half* symaddrh(const void* s) {
    void* p = nullptr;
    cudaGetSymbolAddress(&p, s);
    return (__half*)p;
}

extern "C" void kernel_launch(void* const* d_in, const int* in_sizes, int n_in,
                              void* d_out, int out_size) {
    const float* img   = (const float*)d_in[0];
    const float* txt   = (const float*)d_in[1];
    const float* cond  = (const float*)d_in[2];
    const float* Wmi   = (const float*)d_in[3];
    const float* bmi   = (const float*)d_in[4];
    const float* Wmt   = (const float*)d_in[5];
    const float* bmt   = (const float*)d_in[6];
    const float* rmsi  = (const float*)d_in[7];
    const float* rmst  = (const float*)d_in[8];
    const float* rmsi2 = (const float*)d_in[9];
    const float* rmst2 = (const float*)d_in[10];
    const float* mur   = (const float*)d_in[11];
    const float* muk   = (const float*)d_in[12];
    const float* muv   = (const float*)d_in[13];
    const float* mug   = (const float*)d_in[14];
    const float* Wr    = (const float*)d_in[15];
    const float* Wk    = (const float*)d_in[16];
    const float* Wv    = (const float*)d_in[17];
    const float* Wg    = (const float*)d_in[18];
    const float* Wo    = (const float*)d_in[19];
    const float* td    = (const float*)d_in[20];
    const float* tf    = (const float*)d_in[21];
    const float* lnw   = (const float*)d_in[22];
    const float* lnb   = (const float*)d_in[23];
    const float* fi1   = (const float*)d_in[24];
    const float* fi2   = (const float*)d_in[25];
    const float* ft1   = (const float*)d_in[26];
    const float* ft2   = (const float*)d_in[27];

    float* p_mod   = symaddr(g_mod);
    float* p_ss    = symaddr(g_ss);
    float* p_ss2   = symaddr(g_ss2);
    float* p_gate  = symaddr(g_gate);
    float* p_r     = symaddr(g_r);
    float* p_k     = symaddr(g_k);
    float* p_v     = symaddr(g_v);
    float* p_y     = symaddr(g_y);
    float* p_attn  = symaddr(g_attn);
    float* p_img1  = symaddr(g_img1);
    float* p_txt1  = symaddr(g_txt1);

    __half* pArkvg = symaddrh(g_Arkvg);
    __half* pAwo   = symaddrh(g_Awo);
    __half* pAfi1  = symaddrh(g_Afi1);
    __half* pAfi2  = symaddrh(g_Afi2);
    __half* pAft1  = symaddrh(g_Aft1);
    __half* pAft2  = symaddrh(g_Aft2);
    __half* pBx4   = symaddrh(g_Bx4);
    __half* pBz    = symaddrh(g_Bz);
    __half* pBh    = symaddrh(g_Bh);
    __half* pBm    = symaddrh(g_Bm);

    float* out_img = (float*)d_out;
    float* out_txt = out_img + IMGSZ;

    cudaFuncSetAttribute(gemm_mma<0>, cudaFuncAttributeMaxDynamicSharedMemorySize, GSMEM);
    cudaFuncSetAttribute(gemm_mma<1>, cudaFuncAttributeMaxDynamicSharedMemorySize, GSMEM);
    cudaFuncSetAttribute(gemm_mma<2>, cudaFuncAttributeMaxDynamicSharedMemorySize, GSMEM);
    cudaFuncSetAttribute(gemm_mma<3>, cudaFuncAttributeMaxDynamicSharedMemorySize, GSMEM);

    // 0) modulation + zero ss accumulators
    prep_k<<<MOD_BLOCKS + ZERO_BLOCKS, 256>>>(cond, Wmi, bmi, Wmt, bmt,
                                              p_mod, p_ss, p_ss2);
    // 1) rkvg weight pack + tiled sumsq of raw inputs
    prep2_k<<<WPK_BLOCKS + SQ_BLOCKS, 256>>>(Wr, Wk, Wv, Wg, img, txt, pArkvg, p_ss);
    // 2) mixed inputs (B,L,C) x4 parts
    bxmix_k<<<dim3(L_ / 32, C_ / 32, B_), 256>>>(img, txt, rmsi, rmst, p_mod, p_ss,
                                                 mur, muk, muv, mug, pBx4);
    // 3) fused rkvg GEMM  (profiled launch)
    gemm_mma<1><<<dim3(L_ / 128, 4096 / 128, B_), 256, GSMEM>>>(
        pArkvg, nullptr, pBx4, nullptr, nullptr, nullptr, p_r, p_k, p_v, p_gate,
        nullptr, nullptr, nullptr, nullptr, 4096, 1024, L_, L_);

    // 4) all remaining weight packs in one launch
    wpackall_k<<<(int)((WPALL + 255) / 256), 256>>>(Wo, fi1, fi2, ft1, ft2,
                                                    pAwo, pAfi1, pAfi2, pAft1, pAft2);

    // 5) scan (128 blocks: (b,h) x m-quarter)
    scan_k<<<B_ * H_ * 4, 256>>>(p_r, p_k, p_v, td, tf, p_y);

    // 6) groupnorm * gate -> fp16 (B,L,C)
    gnorm_k<<<dim3(L_ / 64, H_, B_), 256>>>(p_y, p_gate, lnw, lnb, pBz);

    // 7) Wo GEMM -> attn (B,C,L)
    gemm_mma<0><<<dim3(L_ / 128, C_ / 128, B_), 256, GSMEM>>>(
        pAwo, nullptr, pBz, p_attn, nullptr, nullptr, nullptr, nullptr, nullptr,
        nullptr, nullptr, nullptr, nullptr, nullptr, C_, 1024, L_, L_);

    // 8) residual (tiled) + rms2 sums
    resid1_k<<<dim3(L_ / 32, C_ / 32, B_), 256>>>(img, txt, p_attn, p_mod,
                                                  p_img1, p_txt1, p_ss2);
    // 9) h build -> merged fp16 B operand for ffn1
    hbuild_k<<<dim3(L_ / 32, C_ / 32, B_), 256>>>(p_img1, p_txt1, rmsi2, rmst2,
                                                  p_mod, p_ss2, pBh);

    // 10) merged FFN1 (img+txt): gelu -> fp16 (B,L,2048)
    gemm_mma<2><<<dim3(L_ / 128, HID_ / 128, B_), 256, GSMEM>>>(
        pAfi1, pAft1, pBh, nullptr, nullptr, pBm, nullptr, nullptr, nullptr,
        nullptr, nullptr, nullptr, nullptr, nullptr, HID_, 1024, L_, LI_);

    // 11) merged FFN2 (img+txt): resid + gate -> out
    gemm_mma<3><<<dim3(L_ / 128, C_ / 128, B_), 256, GSMEM>>>(
        pAfi2, pAft2, pBm, out_img, out_txt, nullptr, nullptr, nullptr, nullptr,
        nullptr, p_img1, p_txt1, p_mod + 5 * C_, p_mod + B_ * 6 * C_ + 5 * C_,
        C_, 2048, L_, LI_);
}

// round 15
// speedup vs baseline: 1.7512x; 1.0026x over previous
#include <cuda_runtime.h>
#include <cuda_fp16.h>
#include <math.h>
#include <stdint.h>

constexpr int B_  = 2;
constexpr int C_  = 1024;
constexpr int H_  = 16;
constexpr int N_  = 64;
constexpr int LI_ = 4096;
constexpr int LT_ = 512;
constexpr int L_  = LI_ + LT_;   // 4608
constexpr int HID_ = 2048;

constexpr size_t XSZ   = (size_t)B_ * C_ * L_;
constexpr size_t IMGSZ = (size_t)B_ * C_ * LI_;
constexpr size_t TXTSZ = (size_t)B_ * C_ * LT_;

// ---------------- static scratch ----------------
__device__ float g_mod[2 * B_ * 6 * C_];
__device__ float g_ss [B_ * L_];
__device__ float g_ss2[B_ * L_];
__device__ float g_gate[XSZ];                        // silu(g) in (B,L,C)
__device__ float g_r[XSZ];                           // (B,H,L,N)
__device__ float g_k[XSZ];
__device__ float g_v[XSZ];
__device__ float g_y[XSZ];
__device__ float g_img1[IMGSZ];
__device__ float g_txt1[TXTSZ];

// fp16 GEMM operands
__device__ __half g_Arkvg[(size_t)4096 * 1024];      // [Wr;Wk;Wv;Wg]
__device__ __half g_Awo [(size_t)1024 * 1024];
__device__ __half g_Afi1[(size_t)2048 * 1024];
__device__ __half g_Afi2[(size_t)1024 * 2048];
__device__ __half g_Aft1[(size_t)2048 * 1024];
__device__ __half g_Aft2[(size_t)1024 * 2048];
__device__ __half g_Bx4[(size_t)4 * B_ * L_ * 1024];
__device__ __half g_Bz [(size_t)B_ * L_  * 1024];
__device__ __half g_Bh [(size_t)B_ * L_  * 1024];    // merged ffn1 B operand
__device__ __half g_Bm [(size_t)B_ * L_  * 2048];    // merged ffn1 out / ffn2 B

// ---------------- helpers ----------------
__device__ __forceinline__ uint32_t smem_u32(const void* p) {
    uint32_t r;
    asm("{ .reg .u64 t; cvta.to.shared.u64 t, %1; cvt.u32.u64 %0, t; }" : "=r"(r) : "l"(p));
    return r;
}
__device__ __forceinline__ void cp16(uint32_t s, const void* g) {
    asm volatile("cp.async.cg.shared.global [%0], [%1], 16;" :: "r"(s), "l"(g));
}
__device__ __forceinline__ void ldsm4(uint32_t* r, uint32_t addr) {
    asm volatile("ldmatrix.sync.aligned.m8n8.x4.shared.b16 {%0,%1,%2,%3},[%4];"
                 : "=r"(r[0]), "=r"(r[1]), "=r"(r[2]), "=r"(r[3]) : "r"(addr));
}
__device__ __forceinline__ void mma16816(float* d, const uint32_t* a, const uint32_t* b) {
    asm volatile("mma.sync.aligned.m16n8k16.row.col.f32.f16.f16.f32 "
                 "{%0,%1,%2,%3},{%4,%5,%6,%7},{%8,%9},{%0,%1,%2,%3};"
                 : "+f"(d[0]), "+f"(d[1]), "+f"(d[2]), "+f"(d[3])
                 : "r"(a[0]), "r"(a[1]), "r"(a[2]), "r"(a[3]), "r"(b[0]), "r"(b[1]));
}
__device__ __forceinline__ float rms_inv(const float* ss, int idx) {
    return rsqrtf(ss[idx] * (1.f / C_) + 1e-6f);
}

// ---------------- prep: modulation (silu inline) + zero ss ----------------
constexpr int MOD_BLOCKS  = (2 * 6 * C_) / 8;    // 1536
constexpr int ZERO_BLOCKS = (2 * B_ * L_) / 256; // 72

__global__ void prep_k(const float* __restrict__ cond,
                       const float* __restrict__ Wimg, const float* __restrict__ bimg,
                       const float* __restrict__ Wtxt, const float* __restrict__ btxt,
                       float* __restrict__ modout, float* __restrict__ ss,
                       float* __restrict__ ss2) {
    if (blockIdx.x < MOD_BLOCKS) {
        int gw = (blockIdx.x * 256 + threadIdx.x) >> 5;
        int lane = threadIdx.x & 31;
        int s = gw / (6 * C_), o = gw % (6 * C_);
        const float* Wp = (s ? Wtxt : Wimg) + (size_t)o * C_;
        float a0 = 0.f, a1 = 0.f;
        for (int c = lane; c < C_; c += 32) {
            float wv = Wp[c];
            float c0 = cond[c], c1 = cond[C_ + c];
            a0 += wv * (c0 / (1.f + expf(-c0)));
            a1 += wv * (c1 / (1.f + expf(-c1)));
        }
        #pragma unroll
        for (int off = 16; off; off >>= 1) {
            a0 += __shfl_down_sync(0xffffffffu, a0, off);
            a1 += __shfl_down_sync(0xffffffffu, a1, off);
        }
        if (lane == 0) {
            float bb = (s ? btxt : bimg)[o];
            modout[(s * B_ + 0) * 6 * C_ + o] = a0 + bb;
            modout[(s * B_ + 1) * 6 * C_ + o] = a1 + bb;
        }
    } else {
        int gid = (blockIdx.x - MOD_BLOCKS) * 256 + threadIdx.x;
        if (gid < B_ * L_) ss[gid] = 0.f;
        else if (gid < 2 * B_ * L_) ss2[gid - B_ * L_] = 0.f;
    }
}

// ---------------- prep2: wpack4 + tiled sumsq of raw img/txt ----------------
constexpr int WPK_BLOCKS = (4 * 1024 * 1024) / 256;          // 16384
constexpr int SQ_BLOCKS  = B_ * (C_ / 32) * (L_ / 32);       // 9216

__global__ void prep2_k(const float* __restrict__ Wr, const float* __restrict__ Wk,
                        const float* __restrict__ Wv, const float* __restrict__ Wg,
                        const float* __restrict__ img, const float* __restrict__ txt,
                        __half* __restrict__ A, float* __restrict__ ss) {
    if (blockIdx.x < WPK_BLOCKS) {
        size_t idx = (size_t)blockIdx.x * 256 + threadIdx.x;
        int p = (int)(idx >> 20);
        size_t rest = idx & 0xFFFFF;
        const float* W = (p == 0) ? Wr : (p == 1) ? Wk : (p == 2) ? Wv : Wg;
        A[idx] = __float2half(W[rest]);
    } else {
        int t = blockIdx.x - WPK_BLOCKS;
        int b = t / ((C_ / 32) * (L_ / 32));
        int rem = t % ((C_ / 32) * (L_ / 32));
        int c0 = (rem / (L_ / 32)) * 32;
        int l0 = (rem % (L_ / 32)) * 32;
        int tx = threadIdx.x & 31, wy = threadIdx.x >> 5;
        const float* src; int Ls, li0;
        if (l0 < LI_) { src = img; Ls = LI_; li0 = l0; }
        else          { src = txt; Ls = LT_; li0 = l0 - LI_; }
        float p = 0.f;
        #pragma unroll
        for (int i = 0; i < 4; i++) {
            int c = c0 + wy + i * 8;
            float v = src[((size_t)b * C_ + c) * Ls + li0 + tx];
            p += v * v;
        }
        __shared__ float red[8][33];
        red[wy][tx] = p;
        __syncthreads();
        if (threadIdx.x < 32) {
            float sacc = 0.f;
            #pragma unroll
            for (int j = 0; j < 8; j++) sacc += red[j][threadIdx.x];
            atomicAdd(&ss[b * L_ + l0 + threadIdx.x], sacc);
        }
    }
}

// ---------------- merged plain weight packs ----------------
constexpr size_t WO_E  = (size_t)1024 * 1024;
constexpr size_t FI1_E = (size_t)2048 * 1024;
constexpr size_t FI2_E = (size_t)1024 * 2048;
constexpr size_t FT1_E = (size_t)2048 * 1024;
constexpr size_t WPALL = WO_E + FI1_E + FI2_E + FT1_E + FI2_E;   // 9M

__global__ void wpackall_k(const float* __restrict__ Wo,  const float* __restrict__ fi1,
                           const float* __restrict__ fi2, const float* __restrict__ ft1,
                           const float* __restrict__ ft2,
                           __half* __restrict__ Awo,  __half* __restrict__ Afi1,
                           __half* __restrict__ Afi2, __half* __restrict__ Aft1,
                           __half* __restrict__ Aft2) {
    size_t idx = (size_t)blockIdx.x * 256 + threadIdx.x;
    if (idx >= WPALL) return;
    if (idx < WO_E) { Awo[idx] = __float2half(Wo[idx]); return; }
    idx -= WO_E;
    if (idx < FI1_E) { Afi1[idx] = __float2half(fi1[idx]); return; }
    idx -= FI1_E;
    if (idx < FI2_E) { Afi2[idx] = __float2half(fi2[idx]); return; }
    idx -= FI2_E;
    if (idx < FT1_E) { Aft1[idx] = __float2half(ft1[idx]); return; }
    idx -= FT1_E;
    Aft2[idx] = __float2half(ft2[idx]);
}

// ---------------- Bx4 build: rms-modulate + mix + transpose ----------------
__global__ void __launch_bounds__(256)
bxmix_k(const float* __restrict__ img, const float* __restrict__ txt,
        const float* __restrict__ rmswi, const float* __restrict__ rmswt,
        const float* __restrict__ mod, const float* __restrict__ ss,
        const float* __restrict__ mur, const float* __restrict__ muk,
        const float* __restrict__ muv, const float* __restrict__ mug,
        __half* __restrict__ out) {
    __shared__ float tileM[32][35];
    int b = blockIdx.z, c0 = blockIdx.y * 32, l0 = blockIdx.x * 32;
    int tx = threadIdx.x & 31, wy = threadIdx.x >> 5;
    int s0 = (l0 < LI_) ? 0 : 1;
    const float* src0 = s0 ? txt : img;
    int Ls0 = s0 ? LT_ : LI_;
    int li0 = s0 ? l0 - LI_ : l0;
    const float* mb0 = mod + (s0 * B_ + b) * 6 * C_;
    const float* rw0 = s0 ? rmswt : rmswi;
    float ivl = rms_inv(ss, b * L_ + l0 + tx);
    #pragma unroll
    for (int i = 0; i < 4; i++) {
        int c = wy + i * 8;
        int cg = c0 + c;
        float raw = src0[((size_t)b * C_ + cg) * Ls0 + li0 + tx];
        tileM[c][1 + tx] = raw * ivl * rw0[cg] * (1.f + mb0[C_ + cg]) + mb0[cg];
        if (tx == 0) {
            float pv = 0.f;
            if (l0 > 0) {
                int lm = l0 - 1;
                int sm = (lm < LI_) ? 0 : 1;
                const float* srcm = sm ? txt : img;
                int Lsm = sm ? LT_ : LI_;
                int lim = sm ? lm - LI_ : lm;
                const float* mbm = mod + (sm * B_ + b) * 6 * C_;
                const float* rwm = sm ? rmswt : rmswi;
                float rm = srcm[((size_t)b * C_ + cg) * Lsm + lim];
                pv = rm * rms_inv(ss, b * L_ + lm) * rwm[cg] * (1.f + mbm[C_ + cg]) + mbm[cg];
            }
            tileM[c][0] = pv;
        }
    }
    __syncthreads();
    int cg = c0 + tx;
    float m_r = mur[cg], m_k = muk[cg], m_v = muv[cg], m_g = mug[cg];
    const size_t PSTR = (size_t)B_ * L_ * 1024;
    #pragma unroll
    for (int i = 0; i < 4; i++) {
        int lrel = wy + i * 8;
        float vl = tileM[tx][1 + lrel];
        float vp = tileM[tx][lrel];
        float d = vp - vl;
        size_t base = ((size_t)b * L_ + l0 + lrel) * 1024 + cg;
        out[base]            = __float2half(vl + m_r * d);
        out[base + PSTR]     = __float2half(vl + m_k * d);
        out[base + 2 * PSTR] = __float2half(vl + m_v * d);
        out[base + 3 * PSTR] = __float2half(vl + m_g * d);
    }
}

// ---------------- mma.sync GEMM: 3-stage cp.async pipeline ----------------
constexpr int STG = 18432;            // 128 rows * 144B per operand stage
constexpr int GSMEM = 6 * STG;

// MODE 1: rkvg -> r/k/v (B,H,L,N) + gate(B,L,C)
// MODE 2: gelu -> fp16 (B,L,M), A selected by l0 vs LSPLIT
// MODE 3: resid + gate -> fp32 split outputs
// MODE 4: attn residual: dst = src + g1*acc, + ss2 atomics (go = ss2)
template <int MODE>
__global__ void __launch_bounds__(256, 2)
gemm_mma(const __half* __restrict__ A, const __half* __restrict__ A2,
         const __half* __restrict__ Bm,
         float* __restrict__ Y, float* __restrict__ Y2, __half* __restrict__ Yh,
         float* __restrict__ ro, float* __restrict__ ko, float* __restrict__ vo,
         float* __restrict__ go,
         const float* __restrict__ resid, const float* __restrict__ resid2,
         const float* __restrict__ gmod, const float* __restrict__ gmod2,
         int M, int K, int Llen, int LSPLIT) {
    extern __shared__ __align__(16) char dsmem[];
    uint32_t sb = smem_u32(dsmem);
    int tid = threadIdx.x, lane = tid & 31, wid = tid >> 5;
    int wm = wid >> 2, wn = wid & 3;
    int b = blockIdx.z, l0 = blockIdx.x * 128, m0 = blockIdx.y * 128;
    const int NT = K >> 6;

    bool second = (MODE >= 2) && (l0 >= LSPLIT);
    const __half* Asel = second ? A2 : A;

    float acc[4][4][4] = {};
    const __half* Ag = Asel + (size_t)m0 * K;
    const __half* Bg;
    if (MODE == 1) {
        int part = m0 >> 10;
        Bg = Bm + (((size_t)(part * B_ + b)) * Llen + l0) * K;
    } else {
        Bg = Bm + ((size_t)b * Llen + l0) * K;
    }

    int r_ld = tid >> 1, seg = tid & 1;
    uint32_t soff = (uint32_t)(r_ld * 144 + seg * 64);
    const __half* Agr = Ag + (size_t)r_ld * K + seg * 32;
    const __half* Bgr = Bg + (size_t)r_ld * K + seg * 32;

    #pragma unroll
    for (int t = 0; t < 2; t++) {
        uint32_t ao = sb + t * STG + soff;
        uint32_t bo = sb + 3 * STG + t * STG + soff;
        #pragma unroll
        for (int j = 0; j < 4; j++) {
            cp16(ao + j * 16, Agr + t * 64 + j * 8);
            cp16(bo + j * 16, Bgr + t * 64 + j * 8);
        }
        asm volatile("cp.async.commit_group;");
    }

    for (int it = 0; it < NT; it++) {
        if (it + 1 < NT) asm volatile("cp.async.wait_group 1;");
        else             asm volatile("cp.async.wait_group 0;");
        __syncthreads();
        if (it + 2 < NT) {
            int st = (it + 2) % 3;
            int ka = (it + 2) * 64;
            uint32_t ao = sb + st * STG + soff;
            uint32_t bo = sb + 3 * STG + st * STG + soff;
            #pragma unroll
            for (int j = 0; j < 4; j++) {
                cp16(ao + j * 16, Agr + ka + j * 8);
                cp16(bo + j * 16, Bgr + ka + j * 8);
            }
            asm volatile("cp.async.commit_group;");
        }
        uint32_t baseA = sb + (it % 3) * STG;
        uint32_t baseB = sb + 3 * STG + (it % 3) * STG;
        #pragma unroll
        for (int kk = 0; kk < 4; kk++) {
            uint32_t a[4][4], bq[2][4];
            #pragma unroll
            for (int ma = 0; ma < 4; ma++)
                ldsm4(a[ma], baseA + (wm * 64 + ma * 16 + (lane & 15)) * 144
                              + kk * 32 + (lane >> 4) * 16);
            #pragma unroll
            for (int nb = 0; nb < 2; nb++)
                ldsm4(bq[nb], baseB + (wn * 32 + nb * 16 + (lane & 7) + ((lane >> 4) & 1) * 8) * 144
                               + kk * 32 + ((lane >> 3) & 1) * 16);
            #pragma unroll
            for (int ma = 0; ma < 4; ma++)
                #pragma unroll
                for (int na = 0; na < 4; na++)
                    mma16816(acc[ma][na], a[ma], &bq[na >> 1][(na & 1) * 2]);
        }
    }

    if (MODE == 3) {
        float* Yo = second ? Y2 : Y;
        const float* rs = second ? resid2 : resid;
        const float* gs = second ? gmod2 : gmod;
        int Lout = second ? (Llen - LSPLIT) : LSPLIT;
        int lb = second ? (l0 - LSPLIT) : l0;
        #pragma unroll
        for (int ma = 0; ma < 4; ma++) {
            #pragma unroll
            for (int hf = 0; hf < 2; hf++) {
                int m = m0 + wm * 64 + ma * 16 + (lane >> 2) + hf * 8;
                size_t ybase = ((size_t)b * M + m) * Lout;
                float gm = gs[b * 6 * C_ + m];
                #pragma unroll
                for (int na = 0; na < 4; na++) {
                    int col = lb + wn * 32 + na * 8 + 2 * (lane & 3);
                    float v0 = acc[ma][na][hf * 2], v1 = acc[ma][na][hf * 2 + 1];
                    float2 rr = *(const float2*)(rs + ybase + col);
                    v0 = rr.x + gm * v0;
                    v1 = rr.y + gm * v1;
                    *(float2*)(Yo + ybase + col) = make_float2(v0, v1);
                }
            }
        }
    } else if (MODE == 4) {
        __syncthreads();
        float* lsum = (float*)dsmem;
        if (tid < 128) lsum[tid] = 0.f;
        __syncthreads();
        const float* src = second ? resid2 : resid;   // raw img/txt
        float* dst = second ? Y2 : Y;                 // img1/txt1
        const float* gs = second ? gmod2 : gmod;      // mod base pre-offset +2C
        int Ls = second ? (Llen - LSPLIT) : LSPLIT;
        int lb = second ? (l0 - LSPLIT) : l0;
        float lacc[8];
        #pragma unroll
        for (int i = 0; i < 8; i++) lacc[i] = 0.f;
        #pragma unroll
        for (int ma = 0; ma < 4; ma++) {
            #pragma unroll
            for (int hf = 0; hf < 2; hf++) {
                int m = m0 + wm * 64 + ma * 16 + (lane >> 2) + hf * 8;
                float gm = gs[b * 6 * C_ + m];
                size_t ybase = ((size_t)b * C_ + m) * Ls;
                #pragma unroll
                for (int na = 0; na < 4; na++) {
                    int col = lb + wn * 32 + na * 8 + 2 * (lane & 3);
                    float2 rr = *(const float2*)(src + ybase + col);
                    float v0 = rr.x + gm * acc[ma][na][hf * 2];
                    float v1 = rr.y + gm * acc[ma][na][hf * 2 + 1];
                    *(float2*)(dst + ybase + col) = make_float2(v0, v1);
                    lacc[na * 2]     += v0 * v0;
                    lacc[na * 2 + 1] += v1 * v1;
                }
            }
        }
        #pragma unroll
        for (int na = 0; na < 8; na++) {
            int lloc = wn * 32 + (na >> 1) * 8 + 2 * (lane & 3) + (na & 1);
            atomicAdd(&lsum[lloc], lacc[na]);
        }
        __syncthreads();
        if (tid < 128) atomicAdd(&go[(size_t)b * L_ + l0 + tid], lsum[tid]);
    } else if (MODE == 1) {
        __syncthreads();
        float* st = (float*)dsmem;
        int part = m0 >> 10;
        int c0 = m0 & 1023;
        #pragma unroll
        for (int ma = 0; ma < 4; ma++)
            #pragma unroll
            for (int na = 0; na < 4; na++)
                #pragma unroll
                for (int e = 0; e < 4; e++) {
                    int hf = e >> 1, j = e & 1;
                    int m = wm * 64 + ma * 16 + (lane >> 2) + hf * 8;
                    int l = wn * 32 + na * 8 + 2 * (lane & 3) + j;
                    float v = acc[ma][na][hf * 2 + j];
                    if (part == 3) v = v / (1.f + expf(-v));
                    st[l * 132 + m] = v;
                }
        __syncthreads();
        int l = tid >> 1, sg = tid & 1;
        const float* sp = st + l * 132 + sg * 64;
        if (part < 3) {
            float* outb = (part == 0) ? ro : (part == 1) ? ko : vo;
            int c = c0 + sg * 64;
            float* op = outb + ((size_t)(b * H_ + (c >> 6)) * L_ + l0 + l) * 64;
            #pragma unroll
            for (int j = 0; j < 64; j += 4)
                *(float4*)(op + j) = *(const float4*)(sp + j);
        } else {
            float* op = go + ((size_t)b * L_ + l0 + l) * C_ + c0 + sg * 64;
            #pragma unroll
            for (int j = 0; j < 64; j += 4)
                *(float4*)(op + j) = *(const float4*)(sp + j);
        }
    } else { // MODE 2: gelu -> fp16 (B,L,M)
        __syncthreads();
        __half* st = (__half*)dsmem;
        #pragma unroll
        for (int ma = 0; ma < 4; ma++)
            #pragma unroll
            for (int na = 0; na < 4; na++)
                #pragma unroll
                for (int e = 0; e < 4; e++) {
                    int hf = e >> 1, j = e & 1;
                    int m = wm * 64 + ma * 16 + (lane >> 2) + hf * 8;
                    int l = wn * 32 + na * 8 + 2 * (lane & 3) + j;
                    float v = acc[ma][na][hf * 2 + j];
                    float t = 0.7978845608f * (v + 0.044715f * v * v * v);
                    v = 0.5f * v * (1.f + tanhf(t));
                    st[l * 136 + m] = __float2half(v);
                }
        __syncthreads();
        int l = tid >> 1, sg = tid & 1;
        const uint4* sp = (const uint4*)(st + l * 136 + sg * 64);
        uint4* op = (uint4*)(Yh + ((size_t)b * Llen + l0 + l) * M + m0 + sg * 64);
        #pragma unroll
        for (int j = 0; j < 8; j++) op[j] = sp[j];
    }
}

// ---------------- RWKV scan: m-split x4, chunked cp.async + shuffle ----------------
constexpr int SCH = 16;
__global__ void __launch_bounds__(256)
scan_k(const float* __restrict__ rr, const float* __restrict__ kk,
       const float* __restrict__ vv, const float* __restrict__ td,
       const float* __restrict__ tf, float* __restrict__ yy) {
    __shared__ __align__(16) float rs[2][SCH * 64];
    __shared__ __align__(16) float ks[2][SCH * 64];
    __shared__ __align__(16) float vs[2][SCH * 64];
    int bh = blockIdx.x >> 2;
    int mh = blockIdx.x & 3;
    int h = bh & (H_ - 1);
    int tid = threadIdx.x;
    int m = tid >> 4, ns = tid & 15;
    size_t base = (size_t)bh * L_ * N_;

    float S[4], w[4], uk[4];
    #pragma unroll
    for (int i = 0; i < 4; i++) {
        int n = ns * 4 + i;
        w[i] = expf(-expf(td[h * N_ + n]));
        uk[i] = tf[h * N_ + n];
        S[i] = 0.f;
    }

    uint32_t sr = smem_u32(rs), sk = smem_u32(ks), sv = smem_u32(vs);
    const int NCH = L_ / SCH;
    uint32_t toff = (uint32_t)tid * 16;

    cp16(sr + toff, rr + base + tid * 4);
    cp16(sk + toff, kk + base + tid * 4);
    cp16(sv + toff, vv + base + tid * 4);
    asm volatile("cp.async.commit_group;");
    asm volatile("cp.async.wait_group 0;");
    __syncthreads();

    int gm = mh * 16 + m;
    for (int ch = 0; ch < NCH; ch++) {
        int q = ch & 1;
        if (ch + 1 < NCH) {
            uint32_t dst = (uint32_t)((q ^ 1) * SCH * 64 * 4) + toff;
            size_t gof = base + (size_t)(ch + 1) * SCH * 64 + tid * 4;
            cp16(sr + dst, rr + gof);
            cp16(sk + dst, kk + gof);
            cp16(sv + dst, vv + gof);
            asm volatile("cp.async.commit_group;");
        }
        const float* rb = rs[q];
        const float* kb = ks[q];
        const float* vb = vs[q];
        size_t yof = base + (size_t)ch * SCH * 64 + gm;
        #pragma unroll 4
        for (int s = 0; s < SCH; s++) {
            const float* rp = rb + s * 64 + ns * 4;
            const float* kp = kb + s * 64 + ns * 4;
            float vm = vb[s * 64 + gm];
            float t = 0.f, qq = 0.f;
            float4 r4 = *(const float4*)rp;
            float4 k4 = *(const float4*)kp;
            float rv[4] = {r4.x, r4.y, r4.z, r4.w};
            float kv[4] = {k4.x, k4.y, k4.z, k4.w};
            #pragma unroll
            for (int j = 0; j < 4; j++) {
                t += rv[j] * S[j];
                qq += rv[j] * uk[j] * kv[j];
                S[j] = w[j] * S[j] + kv[j] * vm;
            }
            t  += __shfl_xor_sync(0xffffffffu, t, 1);
            t  += __shfl_xor_sync(0xffffffffu, t, 2);
            t  += __shfl_xor_sync(0xffffffffu, t, 4);
            t  += __shfl_xor_sync(0xffffffffu, t, 8);
            qq += __shfl_xor_sync(0xffffffffu, qq, 1);
            qq += __shfl_xor_sync(0xffffffffu, qq, 2);
            qq += __shfl_xor_sync(0xffffffffu, qq, 4);
            qq += __shfl_xor_sync(0xffffffffu, qq, 8);
            if (ns == 0) yy[yof + (size_t)s * 64] = t + qq * vm;
        }
        if (ch + 1 < NCH) asm volatile("cp.async.wait_group 0;");
        __syncthreads();
    }
}

// ---------------- groupnorm * ln_x * gate -> fp16 (B,L,C) ----------------
__global__ void __launch_bounds__(256)
gnorm_k(const float* __restrict__ yy, const float* __restrict__ gate,
        const float* __restrict__ lnw, const float* __restrict__ lnb,
        __half* __restrict__ z) {
    int b = blockIdx.z, h = blockIdx.y, l0 = blockIdx.x * 64;
    __shared__ float tile[64][65];
    __shared__ float rs1[4][64], rs2[4][64];
    __shared__ float smean[64], sinv[64];
    int tid = threadIdx.x;
    size_t ybase = ((size_t)(b * H_ + h) * L_ + l0) * N_;

    #pragma unroll
    for (int i = 0; i < 16; i++) {
        int id = tid + i * 256;
        int row = id >> 6, col = id & 63;
        tile[col][row] = yy[ybase + (size_t)row * N_ + col];
    }
    __syncthreads();
    {
        int l = tid & 63, part = tid >> 6;
        float s1 = 0.f, s2 = 0.f;
        #pragma unroll
        for (int i = 0; i < 16; i++) {
            float v = tile[part * 16 + i][l];
            s1 += v; s2 += v * v;
        }
        rs1[part][l] = s1; rs2[part][l] = s2;
    }
    __syncthreads();
    if (tid < 64) {
        float s1 = rs1[0][tid] + rs1[1][tid] + rs1[2][tid] + rs1[3][tid];
        float s2 = rs2[0][tid] + rs2[1][tid] + rs2[2][tid] + rs2[3][tid];
        float mean = s1 * (1.f / 64);
        float var = s2 * (1.f / 64) - mean * mean;
        smean[tid] = mean;
        sinv[tid] = rsqrtf(var + 1e-5f);
    }
    __syncthreads();

    int n = tid >> 2, lq = tid & 3;
    int c = h * 64 + n;
    float lw = lnw[c], lb = lnb[c];
    #pragma unroll
    for (int q = 0; q < 16; q++) {
        int l = lq * 16 + q;
        size_t rofs = ((size_t)b * L_ + l0 + l) * C_ + c;
        float v = ((tile[n][l] - smean[l]) * sinv[l] * lw + lb) * gate[rofs];
        z[rofs] = __float2half(v);
    }
}

// ---------------- hbuild: rms2-modulate img1/txt1 -> fp16 merged (B,L,C) ------
__global__ void __launch_bounds__(256)
hbuild_k(const float* __restrict__ img1, const float* __restrict__ txt1,
         const float* __restrict__ rmsi2, const float* __restrict__ rmst2,
         const float* __restrict__ mod, const float* __restrict__ ss2,
         __half* __restrict__ bh) {
    __shared__ float tile[32][33];
    __shared__ float sinv[32];
    int b = blockIdx.z, c0 = blockIdx.y * 32, l0 = blockIdx.x * 32;
    int tx = threadIdx.x & 31, wy = threadIdx.x >> 5;
    int s0 = (l0 < LI_) ? 0 : 1;
    const float* src = s0 ? txt1 : img1;
    const float* rw = s0 ? rmst2 : rmsi2;
    int Ls = s0 ? LT_ : LI_;
    int li0 = s0 ? l0 - LI_ : l0;
    const float* mb = mod + (s0 * B_ + b) * 6 * C_;
    #pragma unroll
    for (int i = 0; i < 4; i++) {
        int c = wy + i * 8;
        tile[c][tx] = src[((size_t)b * C_ + c0 + c) * Ls + li0 + tx];
    }
    if (threadIdx.x < 32)
        sinv[threadIdx.x] = rms_inv(ss2, b * L_ + l0 + threadIdx.x);
    __syncthreads();
    int c = c0 + tx;
    float a = rw[c] * (1.f + mb[4 * C_ + c]);
    float sh = mb[3 * C_ + c];
    #pragma unroll
    for (int i = 0; i < 4; i++) {
        int l = wy + i * 8;
        float v = tile[tx][l] * sinv[l] * a + sh;
        bh[((size_t)b * L_ + l0 + l) * 1024 + c] = __float2half(v);
    }
}

// ---------------- host ----------------
static float* symaddr(const void* s) {
    void* p = nullptr;
    cudaGetSymbolAddress(&p, s);
    return (float*)p;
}
static __half* symaddrh(const void* s) {
    void* p = nullptr;
    cudaGetSymbolAddress(&p, s);
    return (__half*)p;
}

extern "C" void kernel_launch(void* const* d_in, const int* in_sizes, int n_in,
                              void* d_out, int out_size) {
    const float* img   = (const float*)d_in[0];
    const float* txt   = (const float*)d_in[1];
    const float* cond  = (const float*)d_in[2];
    const float* Wmi   = (const float*)d_in[3];
    const float* bmi   = (const float*)d_in[4];
    const float* Wmt   = (const float*)d_in[5];
    const float* bmt   = (const float*)d_in[6];
    const float* rmsi  = (const float*)d_in[7];
    const float* rmst  = (const float*)d_in[8];
    const float* rmsi2 = (const float*)d_in[9];
    const float* rmst2 = (const float*)d_in[10];
    const float* mur   = (const float*)d_in[11];
    const float* muk   = (const float*)d_in[12];
    const float* muv   = (const float*)d_in[13];
    const float* mug   = (const float*)d_in[14];
    const float* Wr    = (const float*)d_in[15];
    const float* Wk    = (const float*)d_in[16];
    const float* Wv    = (const float*)d_in[17];
    const float* Wg    = (const float*)d_in[18];
    const float* Wo    = (const float*)d_in[19];
    const float* td    = (const float*)d_in[20];
    const float* tf    = (const float*)d_in[21];
    const float* lnw   = (const float*)d_in[22];
    const float* lnb   = (const float*)d_in[23];
    const float* fi1   = (const float*)d_in[24];
    const float* fi2   = (const float*)d_in[25];
    const float* ft1   = (const float*)d_in[26];
    const float* ft2   = (const float*)d_in[27];

    float* p_mod   = symaddr(g_mod);
    float* p_ss    = symaddr(g_ss);
    float* p_ss2   = symaddr(g_ss2);
    float* p_gate  = symaddr(g_gate);
    float* p_r     = symaddr(g_r);
    float* p_k     = symaddr(g_k);
    float* p_v     = symaddr(g_v);
    float* p_y     = symaddr(g_y);
    float* p_img1  = symaddr(g_img1);
    float* p_txt1  = symaddr(g_txt1);

    __half* pArkvg = symaddrh(g_Arkvg);
    __half* pAwo   = symaddrh(g_Awo);
    __half* pAfi1  = symaddrh(g_Afi1);
    __half* pAfi2  = symaddrh(g_Afi2);
    __half* pAft1  = symaddrh(g_Aft1);
    __half* pAft2  = symaddrh(g_Aft2);
    __half* pBx4   = symaddrh(g_Bx4);
    __half* pBz    = symaddrh(g_Bz);
    __half* pBh    = symaddrh(g_Bh);
    __half* pBm    = symaddrh(g_Bm);

    float* out_img = (float*)d_out;
    float* out_txt = out_img + IMGSZ;

    cudaFuncSetAttribute(gemm_mma<1>, cudaFuncAttributeMaxDynamicSharedMemorySize, GSMEM);
    cudaFuncSetAttribute(gemm_mma<2>, cudaFuncAttributeMaxDynamicSharedMemorySize, GSMEM);
    cudaFuncSetAttribute(gemm_mma<3>, cudaFuncAttributeMaxDynamicSharedMemorySize, GSMEM);
    cudaFuncSetAttribute(gemm_mma<4>, cudaFuncAttributeMaxDynamicSharedMemorySize, GSMEM);

    // 0) modulation + zero ss accumulators
    prep_k<<<MOD_BLOCKS + ZERO_BLOCKS, 256>>>(cond, Wmi, bmi, Wmt, bmt,
                                              p_mod, p_ss, p_ss2);
    // 1) rkvg weight pack + tiled sumsq of raw inputs
    prep2_k<<<WPK_BLOCKS + SQ_BLOCKS, 256>>>(Wr, Wk, Wv, Wg, img, txt, pArkvg, p_ss);
    // 2) mixed inputs (B,L,C) x4 parts
    bxmix_k<<<dim3(L_ / 32, C_ / 32, B_), 256>>>(img, txt, rmsi, rmst, p_mod, p_ss,
                                                 mur, muk, muv, mug, pBx4);
    // 3) fused rkvg GEMM  (profiled launch)
    gemm_mma<1><<<dim3(L_ / 128, 4096 / 128, B_), 256, GSMEM>>>(
        pArkvg, nullptr, pBx4, nullptr, nullptr, nullptr, p_r, p_k, p_v, p_gate,
        nullptr, nullptr, nullptr, nullptr, 4096, 1024, L_, L_);

    // 4) all remaining weight packs in one launch
    wpackall_k<<<(int)((WPALL + 255) / 256), 256>>>(Wo, fi1, fi2, ft1, ft2,
                                                    pAwo, pAfi1, pAfi2, pAft1, pAft2);

    // 5) scan (128 blocks: (b,h) x m-quarter)
    scan_k<<<B_ * H_ * 4, 256>>>(p_r, p_k, p_v, td, tf, p_y);

    // 6) groupnorm * gate -> fp16 (B,L,C)
    gnorm_k<<<dim3(L_ / 64, H_, B_), 256>>>(p_y, p_gate, lnw, lnb, pBz);

    // 7) Wo GEMM with fused attn residual: img1/txt1 = src + g1*attn, + ss2
    gemm_mma<4><<<dim3(L_ / 128, C_ / 128, B_), 256, GSMEM>>>(
        pAwo, pAwo, pBz, p_img1, p_txt1, nullptr, nullptr, nullptr, nullptr,
        p_ss2, img, txt, p_mod + 2 * C_, p_mod + B_ * 6 * C_ + 2 * C_,
        C_, 1024, L_, LI_);

    // 8) h build -> merged fp16 B operand for ffn1
    hbuild_k<<<dim3(L_ / 32, C_ / 32, B_), 256>>>(p_img1, p_txt1, rmsi2, rmst2,
                                                  p_mod, p_ss2, pBh);

    // 9) merged FFN1 (img+txt): gelu -> fp16 (B,L,2048)
    gemm_mma<2><<<dim3(L_ / 128, HID_ / 128, B_), 256, GSMEM>>>(
        pAfi1, pAft1, pBh, nullptr, nullptr, pBm, nullptr, nullptr, nullptr,
        nullptr, nullptr, nullptr, nullptr, nullptr, HID_, 1024, L_, LI_);

    // 10) merged FFN2 (img+txt): resid + gate -> out
    gemm_mma<3><<<dim3(L_ / 128, C_ / 128, B_), 256, GSMEM>>>(
        pAfi2, pAft2, pBm, out_img, out_txt, nullptr, nullptr, nullptr, nullptr,
        nullptr, p_img1, p_txt1, p_mod + 5 * C_, p_mod + B_ * 6 * C_ + 5 * C_,
        C_, 2048, L_, LI_);
}

// round 17
// speedup vs baseline: 1.7816x; 1.0173x over previous
#include <cuda_runtime.h>
#include <cuda_fp16.h>
#include <math.h>
#include <stdint.h>

constexpr int B_  = 2;
constexpr int C_  = 1024;
constexpr int H_  = 16;
constexpr int N_  = 64;
constexpr int LI_ = 4096;
constexpr int LT_ = 512;
constexpr int L_  = LI_ + LT_;   // 4608
constexpr int HID_ = 2048;

constexpr size_t XSZ   = (size_t)B_ * C_ * L_;
constexpr size_t IMGSZ = (size_t)B_ * C_ * LI_;
constexpr size_t TXTSZ = (size_t)B_ * C_ * LT_;

// ---------------- static scratch ----------------
__device__ float g_mod[2 * B_ * 6 * C_];
__device__ float g_ss [B_ * L_];
__device__ float g_ss2[B_ * L_];
__device__ __half g_gate[XSZ];                       // silu(g) in (B,L,C) fp16
__device__ __half g_r[XSZ];                          // (B,H,L,N) fp16
__device__ __half g_k[XSZ];
__device__ __half g_v[XSZ];
__device__ __half g_y[XSZ];                          // scan out fp16
__device__ float g_img1[IMGSZ];
__device__ float g_txt1[TXTSZ];

// fp16 GEMM operands
__device__ __half g_Arkvg[(size_t)4096 * 1024];      // [Wr;Wk;Wv;Wg]
__device__ __half g_Awo [(size_t)1024 * 1024];
__device__ __half g_Afi1[(size_t)2048 * 1024];
__device__ __half g_Afi2[(size_t)1024 * 2048];
__device__ __half g_Aft1[(size_t)2048 * 1024];
__device__ __half g_Aft2[(size_t)1024 * 2048];
__device__ __half g_Bx4[(size_t)4 * B_ * L_ * 1024];
__device__ __half g_Bz [(size_t)B_ * L_  * 1024];
__device__ __half g_Bh [(size_t)B_ * L_  * 1024];    // merged ffn1 B operand
__device__ __half g_Bm [(size_t)B_ * L_  * 2048];    // merged ffn1 out / ffn2 B

// ---------------- helpers ----------------
__device__ __forceinline__ uint32_t smem_u32(const void* p) {
    uint32_t r;
    asm("{ .reg .u64 t; cvta.to.shared.u64 t, %1; cvt.u32.u64 %0, t; }" : "=r"(r) : "l"(p));
    return r;
}
__device__ __forceinline__ void cp16(uint32_t s, const void* g) {
    asm volatile("cp.async.cg.shared.global [%0], [%1], 16;" :: "r"(s), "l"(g));
}
__device__ __forceinline__ void cp8(uint32_t s, const void* g) {
    asm volatile("cp.async.ca.shared.global [%0], [%1], 8;" :: "r"(s), "l"(g));
}
__device__ __forceinline__ void ldsm4(uint32_t* r, uint32_t addr) {
    asm volatile("ldmatrix.sync.aligned.m8n8.x4.shared.b16 {%0,%1,%2,%3},[%4];"
                 : "=r"(r[0]), "=r"(r[1]), "=r"(r[2]), "=r"(r[3]) : "r"(addr));
}
__device__ __forceinline__ void mma16816(float* d, const uint32_t* a, const uint32_t* b) {
    asm volatile("mma.sync.aligned.m16n8k16.row.col.f32.f16.f16.f32 "
                 "{%0,%1,%2,%3},{%4,%5,%6,%7},{%8,%9},{%0,%1,%2,%3};"
                 : "+f"(d[0]), "+f"(d[1]), "+f"(d[2]), "+f"(d[3])
                 : "r"(a[0]), "r"(a[1]), "r"(a[2]), "r"(a[3]), "r"(b[0]), "r"(b[1]));
}
__device__ __forceinline__ float rms_inv(const float* ss, int idx) {
    return rsqrtf(ss[idx] * (1.f / C_) + 1e-6f);
}

// ---------------- prep: modulation (silu inline) + zero ss ----------------
constexpr int MOD_BLOCKS  = (2 * 6 * C_) / 8;    // 1536
constexpr int ZERO_BLOCKS = (2 * B_ * L_) / 256; // 72

__global__ void prep_k(const float* __restrict__ cond,
                       const float* __restrict__ Wimg, const float* __restrict__ bimg,
                       const float* __restrict__ Wtxt, const float* __restrict__ btxt,
                       float* __restrict__ modout, float* __restrict__ ss,
                       float* __restrict__ ss2) {
    if (blockIdx.x < MOD_BLOCKS) {
        int gw = (blockIdx.x * 256 + threadIdx.x) >> 5;
        int lane = threadIdx.x & 31;
        int s = gw / (6 * C_), o = gw % (6 * C_);
        const float* Wp = (s ? Wtxt : Wimg) + (size_t)o * C_;
        float a0 = 0.f, a1 = 0.f;
        for (int c = lane; c < C_; c += 32) {
            float wv = Wp[c];
            float c0 = cond[c], c1 = cond[C_ + c];
            a0 += wv * (c0 / (1.f + expf(-c0)));
            a1 += wv * (c1 / (1.f + expf(-c1)));
        }
        #pragma unroll
        for (int off = 16; off; off >>= 1) {
            a0 += __shfl_down_sync(0xffffffffu, a0, off);
            a1 += __shfl_down_sync(0xffffffffu, a1, off);
        }
        if (lane == 0) {
            float bb = (s ? btxt : bimg)[o];
            modout[(s * B_ + 0) * 6 * C_ + o] = a0 + bb;
            modout[(s * B_ + 1) * 6 * C_ + o] = a1 + bb;
        }
    } else {
        int gid = (blockIdx.x - MOD_BLOCKS) * 256 + threadIdx.x;
        if (gid < B_ * L_) ss[gid] = 0.f;
        else if (gid < 2 * B_ * L_) ss2[gid - B_ * L_] = 0.f;
    }
}

// ---------------- prep2: wpack4 + tiled sumsq of raw img/txt ----------------
constexpr int WPK_BLOCKS = (4 * 1024 * 1024) / 256;          // 16384
constexpr int SQ_BLOCKS  = B_ * (C_ / 32) * (L_ / 32);       // 9216

__global__ void prep2_k(const float* __restrict__ Wr, const float* __restrict__ Wk,
                        const float* __restrict__ Wv, const float* __restrict__ Wg,
                        const float* __restrict__ img, const float* __restrict__ txt,
                        __half* __restrict__ A, float* __restrict__ ss) {
    if (blockIdx.x < WPK_BLOCKS) {
        size_t idx = (size_t)blockIdx.x * 256 + threadIdx.x;
        int p = (int)(idx >> 20);
        size_t rest = idx & 0xFFFFF;
        const float* W = (p == 0) ? Wr : (p == 1) ? Wk : (p == 2) ? Wv : Wg;
        A[idx] = __float2half(W[rest]);
    } else {
        int t = blockIdx.x - WPK_BLOCKS;
        int b = t / ((C_ / 32) * (L_ / 32));
        int rem = t % ((C_ / 32) * (L_ / 32));
        int c0 = (rem / (L_ / 32)) * 32;
        int l0 = (rem % (L_ / 32)) * 32;
        int tx = threadIdx.x & 31, wy = threadIdx.x >> 5;
        const float* src; int Ls, li0;
        if (l0 < LI_) { src = img; Ls = LI_; li0 = l0; }
        else          { src = txt; Ls = LT_; li0 = l0 - LI_; }
        float p = 0.f;
        #pragma unroll
        for (int i = 0; i < 4; i++) {
            int c = c0 + wy + i * 8;
            float v = src[((size_t)b * C_ + c) * Ls + li0 + tx];
            p += v * v;
        }
        __shared__ float red[8][33];
        red[wy][tx] = p;
        __syncthreads();
        if (threadIdx.x < 32) {
            float sacc = 0.f;
            #pragma unroll
            for (int j = 0; j < 8; j++) sacc += red[j][threadIdx.x];
            atomicAdd(&ss[b * L_ + l0 + threadIdx.x], sacc);
        }
    }
}

// ---------------- merged plain weight packs ----------------
constexpr size_t WO_E  = (size_t)1024 * 1024;
constexpr size_t FI1_E = (size_t)2048 * 1024;
constexpr size_t FI2_E = (size_t)1024 * 2048;
constexpr size_t FT1_E = (size_t)2048 * 1024;
constexpr size_t WPALL = WO_E + FI1_E + FI2_E + FT1_E + FI2_E;   // 9M

__global__ void wpackall_k(const float* __restrict__ Wo,  const float* __restrict__ fi1,
                           const float* __restrict__ fi2, const float* __restrict__ ft1,
                           const float* __restrict__ ft2,
                           __half* __restrict__ Awo,  __half* __restrict__ Afi1,
                           __half* __restrict__ Afi2, __half* __restrict__ Aft1,
                           __half* __restrict__ Aft2) {
    size_t idx = (size_t)blockIdx.x * 256 + threadIdx.x;
    if (idx >= WPALL) return;
    if (idx < WO_E) { Awo[idx] = __float2half(Wo[idx]); return; }
    idx -= WO_E;
    if (idx < FI1_E) { Afi1[idx] = __float2half(fi1[idx]); return; }
    idx -= FI1_E;
    if (idx < FI2_E) { Afi2[idx] = __float2half(fi2[idx]); return; }
    idx -= FI2_E;
    if (idx < FT1_E) { Aft1[idx] = __float2half(ft1[idx]); return; }
    idx -= FT1_E;
    Aft2[idx] = __float2half(ft2[idx]);
}

// ---------------- Bx4 build: rms-modulate + mix + transpose ----------------
__global__ void __launch_bounds__(256)
bxmix_k(const float* __restrict__ img, const float* __restrict__ txt,
        const float* __restrict__ rmswi, const float* __restrict__ rmswt,
        const float* __restrict__ mod, const float* __restrict__ ss,
        const float* __restrict__ mur, const float* __restrict__ muk,
        const float* __restrict__ muv, const float* __restrict__ mug,
        __half* __restrict__ out) {
    __shared__ float tileM[32][35];
    int b = blockIdx.z, c0 = blockIdx.y * 32, l0 = blockIdx.x * 32;
    int tx = threadIdx.x & 31, wy = threadIdx.x >> 5;
    int s0 = (l0 < LI_) ? 0 : 1;
    const float* src0 = s0 ? txt : img;
    int Ls0 = s0 ? LT_ : LI_;
    int li0 = s0 ? l0 - LI_ : l0;
    const float* mb0 = mod + (s0 * B_ + b) * 6 * C_;
    const float* rw0 = s0 ? rmswt : rmswi;
    float ivl = rms_inv(ss, b * L_ + l0 + tx);
    #pragma unroll
    for (int i = 0; i < 4; i++) {
        int c = wy + i * 8;
        int cg = c0 + c;
        float raw = src0[((size_t)b * C_ + cg) * Ls0 + li0 + tx];
        tileM[c][1 + tx] = raw * ivl * rw0[cg] * (1.f + mb0[C_ + cg]) + mb0[cg];
        if (tx == 0) {
            float pv = 0.f;
            if (l0 > 0) {
                int lm = l0 - 1;
                int sm = (lm < LI_) ? 0 : 1;
                const float* srcm = sm ? txt : img;
                int Lsm = sm ? LT_ : LI_;
                int lim = sm ? lm - LI_ : lm;
                const float* mbm = mod + (sm * B_ + b) * 6 * C_;
                const float* rwm = sm ? rmswt : rmswi;
                float rm = srcm[((size_t)b * C_ + cg) * Lsm + lim];
                pv = rm * rms_inv(ss, b * L_ + lm) * rwm[cg] * (1.f + mbm[C_ + cg]) + mbm[cg];
            }
            tileM[c][0] = pv;
        }
    }
    __syncthreads();
    int cg = c0 + tx;
    float m_r = mur[cg], m_k = muk[cg], m_v = muv[cg], m_g = mug[cg];
    const size_t PSTR = (size_t)B_ * L_ * 1024;
    #pragma unroll
    for (int i = 0; i < 4; i++) {
        int lrel = wy + i * 8;
        float vl = tileM[tx][1 + lrel];
        float vp = tileM[tx][lrel];
        float d = vp - vl;
        size_t base = ((size_t)b * L_ + l0 + lrel) * 1024 + cg;
        out[base]            = __float2half(vl + m_r * d);
        out[base + PSTR]     = __float2half(vl + m_k * d);
        out[base + 2 * PSTR] = __float2half(vl + m_v * d);
        out[base + 3 * PSTR] = __float2half(vl + m_g * d);
    }
}

// ---------------- mma.sync GEMM: 3-stage cp.async pipeline ----------------
constexpr int STG = 18432;            // 128 rows * 144B per operand stage
constexpr int GSMEM = 6 * STG;

// MODE 1: rkvg -> r/k/v (B,H,L,N) fp16 + gate(B,L,C) fp16
// MODE 2: gelu -> fp16 (B,L,M), A selected by l0 vs LSPLIT
// MODE 3: resid + gate -> fp32 split outputs
// MODE 4: attn residual: dst = src + g1*acc, + ss2 atomics
template <int MODE>
__global__ void __launch_bounds__(256, 2)
gemm_mma(const __half* __restrict__ A, const __half* __restrict__ A2,
         const __half* __restrict__ Bm,
         float* __restrict__ Y, float* __restrict__ Y2, __half* __restrict__ Yh,
         __half* __restrict__ ro, __half* __restrict__ ko, __half* __restrict__ vo,
         __half* __restrict__ go, float* __restrict__ ss2,
         const float* __restrict__ resid, const float* __restrict__ resid2,
         const float* __restrict__ gmod, const float* __restrict__ gmod2,
         int M, int K, int Llen, int LSPLIT) {
    extern __shared__ __align__(16) char dsmem[];
    uint32_t sb = smem_u32(dsmem);
    int tid = threadIdx.x, lane = tid & 31, wid = tid >> 5;
    int wm = wid >> 2, wn = wid & 3;
    int b = blockIdx.z, l0 = blockIdx.x * 128, m0 = blockIdx.y * 128;
    const int NT = K >> 6;

    bool second = (MODE >= 2) && (l0 >= LSPLIT);
    const __half* Asel = second ? A2 : A;

    float acc[4][4][4] = {};
    const __half* Ag = Asel + (size_t)m0 * K;
    const __half* Bg;
    if (MODE == 1) {
        int part = m0 >> 10;
        Bg = Bm + (((size_t)(part * B_ + b)) * Llen + l0) * K;
    } else {
        Bg = Bm + ((size_t)b * Llen + l0) * K;
    }

    int r_ld = tid >> 1, seg = tid & 1;
    uint32_t soff = (uint32_t)(r_ld * 144 + seg * 64);
    const __half* Agr = Ag + (size_t)r_ld * K + seg * 32;
    const __half* Bgr = Bg + (size_t)r_ld * K + seg * 32;

    #pragma unroll
    for (int t = 0; t < 2; t++) {
        uint32_t ao = sb + t * STG + soff;
        uint32_t bo = sb + 3 * STG + t * STG + soff;
        #pragma unroll
        for (int j = 0; j < 4; j++) {
            cp16(ao + j * 16, Agr + t * 64 + j * 8);
            cp16(bo + j * 16, Bgr + t * 64 + j * 8);
        }
        asm volatile("cp.async.commit_group;");
    }

    for (int it = 0; it < NT; it++) {
        if (it + 1 < NT) asm volatile("cp.async.wait_group 1;");
        else             asm volatile("cp.async.wait_group 0;");
        __syncthreads();
        if (it + 2 < NT) {
            int st = (it + 2) % 3;
            int ka = (it + 2) * 64;
            uint32_t ao = sb + st * STG + soff;
            uint32_t bo = sb + 3 * STG + st * STG + soff;
            #pragma unroll
            for (int j = 0; j < 4; j++) {
                cp16(ao + j * 16, Agr + ka + j * 8);
                cp16(bo + j * 16, Bgr + ka + j * 8);
            }
            asm volatile("cp.async.commit_group;");
        }
        uint32_t baseA = sb + (it % 3) * STG;
        uint32_t baseB = sb + 3 * STG + (it % 3) * STG;
        #pragma unroll
        for (int kk = 0; kk < 4; kk++) {
            uint32_t a[4][4], bq[2][4];
            #pragma unroll
            for (int ma = 0; ma < 4; ma++)
                ldsm4(a[ma], baseA + (wm * 64 + ma * 16 + (lane & 15)) * 144
                              + kk * 32 + (lane >> 4) * 16);
            #pragma unroll
            for (int nb = 0; nb < 2; nb++)
                ldsm4(bq[nb], baseB + (wn * 32 + nb * 16 + (lane & 7) + ((lane >> 4) & 1) * 8) * 144
                               + kk * 32 + ((lane >> 3) & 1) * 16);
            #pragma unroll
            for (int ma = 0; ma < 4; ma++)
                #pragma unroll
                for (int na = 0; na < 4; na++)
                    mma16816(acc[ma][na], a[ma], &bq[na >> 1][(na & 1) * 2]);
        }
    }

    if (MODE == 3) {
        float* Yo = second ? Y2 : Y;
        const float* rs = second ? resid2 : resid;
        const float* gs = second ? gmod2 : gmod;
        int Lout = second ? (Llen - LSPLIT) : LSPLIT;
        int lb = second ? (l0 - LSPLIT) : l0;
        #pragma unroll
        for (int ma = 0; ma < 4; ma++) {
            #pragma unroll
            for (int hf = 0; hf < 2; hf++) {
                int m = m0 + wm * 64 + ma * 16 + (lane >> 2) + hf * 8;
                size_t ybase = ((size_t)b * M + m) * Lout;
                float gm = gs[b * 6 * C_ + m];
                #pragma unroll
                for (int na = 0; na < 4; na++) {
                    int col = lb + wn * 32 + na * 8 + 2 * (lane & 3);
                    float v0 = acc[ma][na][hf * 2], v1 = acc[ma][na][hf * 2 + 1];
                    float2 rr = *(const float2*)(rs + ybase + col);
                    v0 = rr.x + gm * v0;
                    v1 = rr.y + gm * v1;
                    *(float2*)(Yo + ybase + col) = make_float2(v0, v1);
                }
            }
        }
    } else if (MODE == 4) {
        __syncthreads();
        float* lsum = (float*)dsmem;
        if (tid < 128) lsum[tid] = 0.f;
        __syncthreads();
        const float* src = second ? resid2 : resid;   // raw img/txt
        float* dst = second ? Y2 : Y;                 // img1/txt1
        const float* gs = second ? gmod2 : gmod;      // mod base pre-offset +2C
        int Ls = second ? (Llen - LSPLIT) : LSPLIT;
        int lb = second ? (l0 - LSPLIT) : l0;
        float lacc[8];
        #pragma unroll
        for (int i = 0; i < 8; i++) lacc[i] = 0.f;
        #pragma unroll
        for (int ma = 0; ma < 4; ma++) {
            #pragma unroll
            for (int hf = 0; hf < 2; hf++) {
                int m = m0 + wm * 64 + ma * 16 + (lane >> 2) + hf * 8;
                float gm = gs[b * 6 * C_ + m];
                size_t ybase = ((size_t)b * C_ + m) * Ls;
                #pragma unroll
                for (int na = 0; na < 4; na++) {
                    int col = lb + wn * 32 + na * 8 + 2 * (lane & 3);
                    float2 rr = *(const float2*)(src + ybase + col);
                    float v0 = rr.x + gm * acc[ma][na][hf * 2];
                    float v1 = rr.y + gm * acc[ma][na][hf * 2 + 1];
                    *(float2*)(dst + ybase + col) = make_float2(v0, v1);
                    lacc[na * 2]     += v0 * v0;
                    lacc[na * 2 + 1] += v1 * v1;
                }
            }
        }
        #pragma unroll
        for (int na = 0; na < 8; na++) {
            int lloc = wn * 32 + (na >> 1) * 8 + 2 * (lane & 3) + (na & 1);
            atomicAdd(&lsum[lloc], lacc[na]);
        }
        __syncthreads();
        if (tid < 128) atomicAdd(&ss2[(size_t)b * L_ + l0 + tid], lsum[tid]);
    } else if (MODE == 1) {
        __syncthreads();
        __half* st = (__half*)dsmem;     // [128 l][136]
        int part = m0 >> 10;
        int c0 = m0 & 1023;
        #pragma unroll
        for (int ma = 0; ma < 4; ma++)
            #pragma unroll
            for (int na = 0; na < 4; na++)
                #pragma unroll
                for (int e = 0; e < 4; e++) {
                    int hf = e >> 1, j = e & 1;
                    int m = wm * 64 + ma * 16 + (lane >> 2) + hf * 8;
                    int l = wn * 32 + na * 8 + 2 * (lane & 3) + j;
                    float v = acc[ma][na][hf * 2 + j];
                    if (part == 3) v = v / (1.f + expf(-v));
                    st[l * 136 + m] = __float2half(v);
                }
        __syncthreads();
        int l = tid >> 1, sg = tid & 1;
        const uint4* sp = (const uint4*)(st + l * 136 + sg * 64);
        if (part < 3) {
            __half* outb = (part == 0) ? ro : (part == 1) ? ko : vo;
            int c = c0 + sg * 64;
            uint4* op = (uint4*)(outb + ((size_t)(b * H_ + (c >> 6)) * L_ + l0 + l) * 64);
            #pragma unroll
            for (int j = 0; j < 8; j++) op[j] = sp[j];
        } else {
            uint4* op = (uint4*)(go + ((size_t)b * L_ + l0 + l) * C_ + c0 + sg * 64);
            #pragma unroll
            for (int j = 0; j < 8; j++) op[j] = sp[j];
        }
    } else { // MODE 2: gelu -> fp16 (B,L,M)
        __syncthreads();
        __half* st = (__half*)dsmem;
        #pragma unroll
        for (int ma = 0; ma < 4; ma++)
            #pragma unroll
            for (int na = 0; na < 4; na++)
                #pragma unroll
                for (int e = 0; e < 4; e++) {
                    int hf = e >> 1, j = e & 1;
                    int m = wm * 64 + ma * 16 + (lane >> 2) + hf * 8;
                    int l = wn * 32 + na * 8 + 2 * (lane & 3) + j;
                    float v = acc[ma][na][hf * 2 + j];
                    float t = 0.7978845608f * (v + 0.044715f * v * v * v);
                    v = 0.5f * v * (1.f + tanhf(t));
                    st[l * 136 + m] = __float2half(v);
                }
        __syncthreads();
        int l = tid >> 1, sg = tid & 1;
        const uint4* sp = (const uint4*)(st + l * 136 + sg * 64);
        uint4* op = (uint4*)(Yh + ((size_t)b * Llen + l0 + l) * M + m0 + sg * 64);
        #pragma unroll
        for (int j = 0; j < 8; j++) op[j] = sp[j];
    }
}

// ---------------- RWKV scan: fp16 i/o, m-split x4, cp.async + shuffle ----------------
constexpr int SCH = 16;
__global__ void __launch_bounds__(256)
scan_k(const __half* __restrict__ rr, const __half* __restrict__ kk,
       const __half* __restrict__ vv, const float* __restrict__ td,
       const float* __restrict__ tf, __half* __restrict__ yy) {
    __shared__ __align__(16) __half rs[2][SCH * 64];
    __shared__ __align__(16) __half ks[2][SCH * 64];
    __shared__ __align__(16) __half vs[2][SCH * 64];
    int bh = blockIdx.x >> 2;
    int mh = blockIdx.x & 3;
    int h = bh & (H_ - 1);
    int tid = threadIdx.x;
    int m = tid >> 4, ns = tid & 15;
    size_t base = (size_t)bh * L_ * N_;

    float S[4], w[4], uk[4];
    #pragma unroll
    for (int i = 0; i < 4; i++) {
        int n = ns * 4 + i;
        w[i] = expf(-expf(td[h * N_ + n]));
        uk[i] = tf[h * N_ + n];
        S[i] = 0.f;
    }

    uint32_t sr = smem_u32(rs), sk = smem_u32(ks), sv = smem_u32(vs);
    const int NCH = L_ / SCH;
    uint32_t toff = (uint32_t)tid * 8;

    cp8(sr + toff, rr + base + tid * 4);
    cp8(sk + toff, kk + base + tid * 4);
    cp8(sv + toff, vv + base + tid * 4);
    asm volatile("cp.async.commit_group;");
    asm volatile("cp.async.wait_group 0;");
    __syncthreads();

    int gm = mh * 16 + m;
    for (int ch = 0; ch < NCH; ch++) {
        int q = ch & 1;
        if (ch + 1 < NCH) {
            uint32_t dst = (uint32_t)((q ^ 1) * SCH * 64 * 2) + toff;
            size_t gof = base + (size_t)(ch + 1) * SCH * 64 + tid * 4;
            cp8(sr + dst, rr + gof);
            cp8(sk + dst, kk + gof);
            cp8(sv + dst, vv + gof);
            asm volatile("cp.async.commit_group;");
        }
        const __half* rb = rs[q];
        const __half* kb = ks[q];
        const __half* vb = vs[q];
        size_t yof = base + (size_t)ch * SCH * 64 + gm;
        #pragma unroll 4
        for (int s = 0; s < SCH; s++) {
            const __half* rp = rb + s * 64 + ns * 4;
            const __half* kp = kb + s * 64 + ns * 4;
            float vm = __half2float(vb[s * 64 + gm]);
            float2 rf0 = __half22float2(*(const __half2*)rp);
            float2 rf1 = __half22float2(*(const __half2*)(rp + 2));
            float2 kf0 = __half22float2(*(const __half2*)kp);
            float2 kf1 = __half22float2(*(const __half2*)(kp + 2));
            float rv[4] = {rf0.x, rf0.y, rf1.x, rf1.y};
            float kv[4] = {kf0.x, kf0.y, kf1.x, kf1.y};
            float t = 0.f, qq = 0.f;
            #pragma unroll
            for (int j = 0; j < 4; j++) {
                t += rv[j] * S[j];
                qq += rv[j] * uk[j] * kv[j];
                S[j] = w[j] * S[j] + kv[j] * vm;
            }
            t  += __shfl_xor_sync(0xffffffffu, t, 1);
            t  += __shfl_xor_sync(0xffffffffu, t, 2);
            t  += __shfl_xor_sync(0xffffffffu, t, 4);
            t  += __shfl_xor_sync(0xffffffffu, t, 8);
            qq += __shfl_xor_sync(0xffffffffu, qq, 1);
            qq += __shfl_xor_sync(0xffffffffu, qq, 2);
            qq += __shfl_xor_sync(0xffffffffu, qq, 4);
            qq += __shfl_xor_sync(0xffffffffu, qq, 8);
            if (ns == 0) yy[yof + (size_t)s * 64] = __float2half(t + qq * vm);
        }
        if (ch + 1 < NCH) asm volatile("cp.async.wait_group 0;");
        __syncthreads();
    }
}

// ---------------- groupnorm * ln_x * gate -> fp16 (B,L,C) ----------------
__global__ void __launch_bounds__(256)
gnorm_k(const __half* __restrict__ yy, const __half* __restrict__ gate,
        const float* __restrict__ lnw, const float* __restrict__ lnb,
        __half* __restrict__ z) {
    int b = blockIdx.z, h = blockIdx.y, l0 = blockIdx.x * 64;
    __shared__ float tile[64][65];
    __shared__ float rs1[4][64], rs2[4][64];
    __shared__ float smean[64], sinv[64];
    int tid = threadIdx.x;
    size_t ybase = ((size_t)(b * H_ + h) * L_ + l0) * N_;

    #pragma unroll
    for (int i = 0; i < 16; i++) {
        int id = tid + i * 256;
        int row = id >> 6, col = id & 63;
        tile[col][row] = __half2float(yy[ybase + (size_t)row * N_ + col]);
    }
    __syncthreads();
    {
        int l = tid & 63, part = tid >> 6;
        float s1 = 0.f, s2 = 0.f;
        #pragma unroll
        for (int i = 0; i < 16; i++) {
            float v = tile[part * 16 + i][l];
            s1 += v; s2 += v * v;
        }
        rs1[part][l] = s1; rs2[part][l] = s2;
    }
    __syncthreads();
    if (tid < 64) {
        float s1 = rs1[0][tid] + rs1[1][tid] + rs1[2][tid] + rs1[3][tid];
        float s2 = rs2[0][tid] + rs2[1][tid] + rs2[2][tid] + rs2[3][tid];
        float mean = s1 * (1.f / 64);
        float var = s2 * (1.f / 64) - mean * mean;
        smean[tid] = mean;
        sinv[tid] = rsqrtf(var + 1e-5f);
    }
    __syncthreads();

    int n = tid >> 2, lq = tid & 3;
    int c = h * 64 + n;
    float lw = lnw[c], lb = lnb[c];
    #pragma unroll
    for (int q = 0; q < 16; q++) {
        int l = lq * 16 + q;
        size_t rofs = ((size_t)b * L_ + l0 + l) * C_ + c;
        float v = ((tile[n][l] - smean[l]) * sinv[l] * lw + lb) * __half2float(gate[rofs]);
        z[rofs] = __float2half(v);
    }
}

// ---------------- hbuild: rms2-modulate img1/txt1 -> fp16 merged (B,L,C) ------
__global__ void __launch_bounds__(256)
hbuild_k(const float* __restrict__ img1, const float* __restrict__ txt1,
         const float* __restrict__ rmsi2, const float* __restrict__ rmst2,
         const float* __restrict__ mod, const float* __restrict__ ss2,
         __half* __restrict__ bh) {
    __shared__ float tile[32][33];
    __shared__ float sinv[32];
    int b = blockIdx.z, c0 = blockIdx.y * 32, l0 = blockIdx.x * 32;
    int tx = threadIdx.x & 31, wy = threadIdx.x >> 5;
    int s0 = (l0 < LI_) ? 0 : 1;
    const float* src = s0 ? txt1 : img1;
    const float* rw = s0 ? rmst2 : rmsi2;
    int Ls = s0 ? LT_ : LI_;
    int li0 = s0 ? l0 - LI_ : l0;
    const float* mb = mod + (s0 * B_ + b) * 6 * C_;
    #pragma unroll
    for (int i = 0; i < 4; i++) {
        int c = wy + i * 8;
        tile[c][tx] = src[((size_t)b * C_ + c0 + c) * Ls + li0 + tx];
    }
    if (threadIdx.x < 32)
        sinv[threadIdx.x] = rms_inv(ss2, b * L_ + l0 + threadIdx.x);
    __syncthreads();
    int c = c0 + tx;
    float a = rw[c] * (1.f + mb[4 * C_ + c]);
    float sh = mb[3 * C_ + c];
    #pragma unroll
    for (int i = 0; i < 4; i++) {
        int l = wy + i * 8;
        float v = tile[tx][l] * sinv[l] * a + sh;
        bh[((size_t)b * L_ + l0 + l) * 1024 + c] = __float2half(v);
    }
}

// ---------------- host ----------------
static float* symaddr(const void* s) {
    void* p = nullptr;
    cudaGetSymbolAddress(&p, s);
    return (float*)p;
}
static __half* symaddrh(const void* s) {
    void* p = nullptr;
    cudaGetSymbolAddress(&p, s);
    return (__half*)p;
}

extern "C" void kernel_launch(void* const* d_in, const int* in_sizes, int n_in,
                              void* d_out, int out_size) {
    const float* img   = (const float*)d_in[0];
    const float* txt   = (const float*)d_in[1];
    const float* cond  = (const float*)d_in[2];
    const float* Wmi   = (const float*)d_in[3];
    const float* bmi   = (const float*)d_in[4];
    const float* Wmt   = (const float*)d_in[5];
    const float* bmt   = (const float*)d_in[6];
    const float* rmsi  = (const float*)d_in[7];
    const float* rmst  = (const float*)d_in[8];
    const float* rmsi2 = (const float*)d_in[9];
    const float* rmst2 = (const float*)d_in[10];
    const float* mur   = (const float*)d_in[11];
    const float* muk   = (const float*)d_in[12];
    const float* muv   = (const float*)d_in[13];
    const float* mug   = (const float*)d_in[14];
    const float* Wr    = (const float*)d_in[15];
    const float* Wk    = (const float*)d_in[16];
    const float* Wv    = (const float*)d_in[17];
    const float* Wg    = (const float*)d_in[18];
    const float* Wo    = (const float*)d_in[19];
    const float* td    = (const float*)d_in[20];
    const float* tf    = (const float*)d_in[21];
    const float* lnw   = (const float*)d_in[22];
    const float* lnb   = (const float*)d_in[23];
    const float* fi1   = (const float*)d_in[24];
    const float* fi2   = (const float*)d_in[25];
    const float* ft1   = (const float*)d_in[26];
    const float* ft2   = (const float*)d_in[27];

    float* p_mod   = symaddr(g_mod);
    float* p_ss    = symaddr(g_ss);
    float* p_ss2   = symaddr(g_ss2);
    __half* p_gate = symaddrh(g_gate);
    __half* p_r    = symaddrh(g_r);
    __half* p_k    = symaddrh(g_k);
    __half* p_v    = symaddrh(g_v);
    __half* p_y    = symaddrh(g_y);
    float* p_img1  = symaddr(g_img1);
    float* p_txt1  = symaddr(g_txt1);

    __half* pArkvg = symaddrh(g_Arkvg);
    __half* pAwo   = symaddrh(g_Awo);
    __half* pAfi1  = symaddrh(g_Afi1);
    __half* pAfi2  = symaddrh(g_Afi2);
    __half* pAft1  = symaddrh(g_Aft1);
    __half* pAft2  = symaddrh(g_Aft2);
    __half* pBx4   = symaddrh(g_Bx4);
    __half* pBz    = symaddrh(g_Bz);
    __half* pBh    = symaddrh(g_Bh);
    __half* pBm    = symaddrh(g_Bm);

    float* out_img = (float*)d_out;
    float* out_txt = out_img + IMGSZ;

    cudaFuncSetAttribute(gemm_mma<1>, cudaFuncAttributeMaxDynamicSharedMemorySize, GSMEM);
    cudaFuncSetAttribute(gemm_mma<2>, cudaFuncAttributeMaxDynamicSharedMemorySize, GSMEM);
    cudaFuncSetAttribute(gemm_mma<3>, cudaFuncAttributeMaxDynamicSharedMemorySize, GSMEM);
    cudaFuncSetAttribute(gemm_mma<4>, cudaFuncAttributeMaxDynamicSharedMemorySize, GSMEM);

    // 0) modulation + zero ss accumulators
    prep_k<<<MOD_BLOCKS + ZERO_BLOCKS, 256>>>(cond, Wmi, bmi, Wmt, bmt,
                                              p_mod, p_ss, p_ss2);
    // 1) rkvg weight pack + tiled sumsq of raw inputs
    prep2_k<<<WPK_BLOCKS + SQ_BLOCKS, 256>>>(Wr, Wk, Wv, Wg, img, txt, pArkvg, p_ss);
    // 2) mixed inputs (B,L,C) x4 parts
    bxmix_k<<<dim3(L_ / 32, C_ / 32, B_), 256>>>(img, txt, rmsi, rmst, p_mod, p_ss,
                                                 mur, muk, muv, mug, pBx4);
    // 3) fused rkvg GEMM  (profiled launch)
    gemm_mma<1><<<dim3(L_ / 128, 4096 / 128, B_), 256, GSMEM>>>(
        pArkvg, nullptr, pBx4, nullptr, nullptr, nullptr, p_r, p_k, p_v, p_gate,
        nullptr, nullptr, nullptr, nullptr, nullptr, 4096, 1024, L_, L_);

    // 4) all remaining weight packs in one launch
    wpackall_k<<<(int)((WPALL + 255) / 256), 256>>>(Wo, fi1, fi2, ft1, ft2,
                                                    pAwo, pAfi1, pAfi2, pAft1, pAft2);

    // 5) scan (128 blocks: (b,h) x m-quarter), fp16 i/o
    scan_k<<<B_ * H_ * 4, 256>>>(p_r, p_k, p_v, td, tf, p_y);

    // 6) groupnorm * gate -> fp16 (B,L,C)
    gnorm_k<<<dim3(L_ / 64, H_, B_), 256>>>(p_y, p_gate, lnw, lnb, pBz);

    // 7) Wo GEMM with fused attn residual: img1/txt1 = src + g1*attn, + ss2
    gemm_mma<4><<<dim3(L_ / 128, C_ / 128, B_), 256, GSMEM>>>(
        pAwo, pAwo, pBz, p_img1, p_txt1, nullptr, nullptr, nullptr, nullptr,
        nullptr, p_ss2, img, txt, p_mod + 2 * C_, p_mod + B_ * 6 * C_ + 2 * C_,
        C_, 1024, L_, LI_);

    // 8) h build -> merged fp16 B operand for ffn1
    hbuild_k<<<dim3(L_ / 32, C_ / 32, B_), 256>>>(p_img1, p_txt1, rmsi2, rmst2,
                                                  p_mod, p_ss2, pBh);

    // 9) merged FFN1 (img+txt): gelu -> fp16 (B,L,2048)
    gemm_mma<2><<<dim3(L_ / 128, HID_ / 128, B_), 256, GSMEM>>>(
        pAfi1, pAft1, pBh, nullptr, nullptr, pBm, nullptr, nullptr, nullptr,
        nullptr, nullptr, nullptr, nullptr, nullptr, nullptr, HID_, 1024, L_, LI_);

    // 10) merged FFN2 (img+txt): resid + gate -> out
    gemm_mma<3><<<dim3(L_ / 128, C_ / 128, B_), 256, GSMEM>>>(
        pAfi2, pAft2, pBm, out_img, out_txt, nullptr, nullptr, nullptr, nullptr,
        nullptr, nullptr, p_img1, p_txt1, p_mod + 5 * C_, p_mod + B_ * 6 * C_ + 5 * C_,
        C_, 2048, L_, LI_);
}